// round 14
// baseline (speedup 1.0000x reference)
#include <cuda_runtime.h>
#include <cuda_fp16.h>
#include <math.h>
#include <stdint.h>

#define D 1024
#define T_SEQ 1024
#define BATCH 4
#define NMEM 16
#define NHEADS 64
#define HD 16
#define ROWS (BATCH*T_SEQ)   // 4096

// ---------------- scratch (device globals; no runtime allocation) ----------------
__device__ __half h_h[ROWS*D];           // LN1/LN3 outputs (fp16)
__device__ __half h_qkv[ROWS*3*D];       // QKV (fp16)
__device__ __half h_ao[ROWS*D];          // self-attention output (fp16)
__device__ __half h_ffn[ROWS*4*D];       // FFN hidden (fp16)
__device__ float g_meanh[BATCH*D];
__device__ float g_base[3*BATCH*D];
__device__ float g_zpre[BATCH*NMEM*D];
__device__ float g_rpre[BATCH*NMEM*D];
__device__ float g_z[BATCH*NMEM*D];
__device__ float g_rm[BATCH*NMEM*D];
__device__ float g_K[BATCH*NMEM*D];      // K' -> K'' = g2 * K' (folded in place)
__device__ float g_V[BATCH*NMEM*D];
__device__ float g_cc[2*BATCH*NMEM];     // c1 = sum(K''), c2 = sum(beta2*K')
__device__ float g_wk[1024*1024];        // Wk' = mq^T @ mk
__device__ float g_wv[1024*1024];        // Wv' = mo @ mv
__device__ float g_w[8*1024*1024];       // float scratch for fold path
__device__ __half h_w[12*1024*1024];     // fp16 weight copies

#define OFF_MQT   0
#define OFF_MO    (1*1024*1024)
#define OFF_MKT   (2*1024*1024)
#define OFF_MVT   (3*1024*1024)
#define HOFF_INP  0
#define HOFF_AOUT (3*1024*1024)
#define HOFF_W1   (4*1024*1024)
#define HOFF_W2   (8*1024*1024)

__device__ __forceinline__ float to_tf32(float v) {
    uint32_t r;
    asm("cvt.rna.tf32.f32 %0, %1;" : "=r"(r) : "f"(v));
    return __uint_as_float(r);
}

// ---------------- utility kernels ----------------
__global__ void cvt_tf32_kernel(const float* __restrict__ src, float* __restrict__ dst, int n4) {
    int i = blockIdx.x*blockDim.x + threadIdx.x;
    if (i < n4) {
        float4 v = ((const float4*)src)[i];
        v.x = to_tf32(v.x); v.y = to_tf32(v.y); v.z = to_tf32(v.z); v.w = to_tf32(v.w);
        ((float4*)dst)[i] = v;
    }
}

__global__ void cvt_fp16_kernel(const float* __restrict__ src, __half* __restrict__ dst, int n4) {
    int i = blockIdx.x*blockDim.x + threadIdx.x;
    if (i < n4) {
        float4 v = ((const float4*)src)[i];
        half2 lo = __floats2half2_rn(v.x, v.y);
        half2 hi = __floats2half2_rn(v.z, v.w);
        ((half2*)dst)[2*i]   = lo;
        ((half2*)dst)[2*i+1] = hi;
    }
}

__global__ __launch_bounds__(256) void transpose_tf32(
    const float* __restrict__ src, float* __restrict__ dst)
{
    __shared__ float tile[32][33];
    int x = blockIdx.x*32 + threadIdx.x;
    int y0 = blockIdx.y*32 + threadIdx.y;
    #pragma unroll
    for (int i=0;i<32;i+=8)
        tile[threadIdx.y+i][threadIdx.x] = src[(size_t)(y0+i)*1024 + x];
    __syncthreads();
    int x2 = blockIdx.y*32 + threadIdx.x;
    int y2 = blockIdx.x*32 + threadIdx.y;
    #pragma unroll
    for (int i=0;i<32;i+=8)
        dst[(size_t)(y2+i)*1024 + x2] = to_tf32(tile[threadIdx.x][threadIdx.y+i]);
}

__global__ __launch_bounds__(256) void ln_kernel_h(
    const float* __restrict__ x, const float* __restrict__ g,
    const float* __restrict__ b, __half* __restrict__ y)
{
    __shared__ float s1[256], s2[256];
    int row = blockIdx.x;
    const float4* xr = (const float4*)(x + (size_t)row*D);
    float4 v = xr[threadIdx.x];
    float sum = v.x+v.y+v.z+v.w;
    float sq  = v.x*v.x + v.y*v.y + v.z*v.z + v.w*v.w;
    s1[threadIdx.x]=sum; s2[threadIdx.x]=sq;
    __syncthreads();
    for (int off=128; off; off>>=1) {
        if (threadIdx.x < off) {
            s1[threadIdx.x]+=s1[threadIdx.x+off];
            s2[threadIdx.x]+=s2[threadIdx.x+off];
        }
        __syncthreads();
    }
    float mean = s1[0]*(1.0f/D);
    float var  = s2[0]*(1.0f/D) - mean*mean;
    float rstd = rsqrtf(var + 1e-5f);
    int c = threadIdx.x*4;
    float4 gg = *(const float4*)(g+c);
    float4 bb = *(const float4*)(b+c);
    half2 lo = __floats2half2_rn((v.x-mean)*rstd*gg.x + bb.x, (v.y-mean)*rstd*gg.y + bb.y);
    half2 hi = __floats2half2_rn((v.z-mean)*rstd*gg.z + bb.z, (v.w-mean)*rstd*gg.w + bb.w);
    half2* yr = (half2*)(y + (size_t)row*D);
    yr[threadIdx.x*2]   = lo;
    yr[threadIdx.x*2+1] = hi;
}

__device__ __forceinline__ void cp16(uint32_t dst, const void* src) {
    asm volatile("cp.async.cg.shared.global [%0], [%1], 16;" :: "r"(dst), "l"(src));
}

#define LDM_X4(r0, r1, r2, r3, addr) \
    asm volatile("ldmatrix.sync.aligned.m8n8.x4.shared.b16 {%0,%1,%2,%3}, [%4];" \
        : "=r"(r0), "=r"(r1), "=r"(r2), "=r"(r3) : "r"(addr))

// ---------------- fp16 tensor-core GEMM: C(M,N) = A(M,K) @ B(N,K)^T -------------
// m16n8k16 HMMA, fp32 accum. 128x128 block, 4 warps (128 thr), 64x64 warp tile,
// BK=32, 4-stage cp.async ring, ldmatrix fragments.
#define HA_OFF(buf) ((buf)*10240)
#define HB_OFF(buf) (5120 + (buf)*10240)
#define HSMEM_BYTES (4*10240*2)   // 81920 B

template<int ACT, int BIASF, int RESF, int OUTHALF>
__global__ __launch_bounds__(128, 2) void gemm_fp16(
    const __half* __restrict__ A, const __half* __restrict__ B,
    const float* __restrict__ bias, const float* __restrict__ res,
    void* __restrict__ Cv, int M, int N, int K)
{
    extern __shared__ __half hsm[];
    float* Cf = (float*)Cv;
    __half* Ch = (__half*)Cv;
    const int tid = threadIdx.x;
    const int bm = blockIdx.y * 128;
    const int bn = blockIdx.x * 128;
    const int lane = tid & 31;
    const int warp = tid >> 5;
    const int wm64 = (warp & 1) * 64;
    const int wn64 = (warp >> 1) * 64;
    const int qr = lane >> 2;
    const int qc = lane & 3;
    uint32_t smem_u32 = (uint32_t)__cvta_generic_to_shared(hsm);

    const int a_row = wm64 + (lane & 7) + ((lane >> 3) & 1) * 8;  // + i*16
    const int a_kk  = (lane >> 4) * 8;
    const int b_row = wn64 + (lane & 7) + ((lane >= 16) ? 8 : 0); // + jp*16
    const int b_kk  = ((lane >> 3) & 1) * 8;

    const int ld_row = tid >> 2;        // 0..31 (+32 per rep)
    const int ld_seg = (tid & 3) * 8;   // halves

    float acc[4][8][4];
    #pragma unroll
    for (int i=0;i<4;i++)
        #pragma unroll
        for (int j=0;j<8;j++)
            #pragma unroll
            for (int e=0;e<4;e++) acc[i][j][e] = 0.f;

    const int NT = K >> 5;

    // prologue: prefetch stages 0..2
    #pragma unroll
    for (int p=0; p<3; p++) {
        const __half* Ab = A + (size_t)bm*K + p*32;
        const __half* Bb = B + (size_t)bn*K + p*32;
        #pragma unroll
        for (int rep=0; rep<4; rep++) {
            int row = rep*32 + ld_row;
            cp16(smem_u32 + (HA_OFF(p) + row*40 + ld_seg)*2, Ab + (size_t)row*K + ld_seg);
            cp16(smem_u32 + (HB_OFF(p) + row*40 + ld_seg)*2, Bb + (size_t)row*K + ld_seg);
        }
        asm volatile("cp.async.commit_group;");
    }

    for (int t = 0; t < NT; t++) {
        if (t + 3 <= NT)      asm volatile("cp.async.wait_group 2;");
        else if (t + 2 == NT) asm volatile("cp.async.wait_group 1;");
        else                  asm volatile("cp.async.wait_group 0;");
        __syncthreads();

        if (t + 3 < NT) {
            int buf = (t+3) & 3;
            int kb = (t+3) << 5;
            const __half* Ab = A + (size_t)bm*K + kb;
            const __half* Bb = B + (size_t)bn*K + kb;
            #pragma unroll
            for (int rep=0; rep<4; rep++) {
                int row = rep*32 + ld_row;
                cp16(smem_u32 + (HA_OFF(buf) + row*40 + ld_seg)*2, Ab + (size_t)row*K + ld_seg);
                cp16(smem_u32 + (HB_OFF(buf) + row*40 + ld_seg)*2, Bb + (size_t)row*K + ld_seg);
            }
            asm volatile("cp.async.commit_group;");
        }

        const uint32_t abuf = HA_OFF(t & 3);
        const uint32_t bbuf = HB_OFF(t & 3);

        #pragma unroll
        for (int ks = 0; ks < 2; ks++) {
            const int k0 = ks * 16;
            uint32_t a[4][4], b[8][2];
            #pragma unroll
            for (int i=0;i<4;i++) {
                uint32_t ad = smem_u32 + (abuf + (a_row + i*16)*40 + k0 + a_kk)*2;
                LDM_X4(a[i][0], a[i][1], a[i][2], a[i][3], ad);
            }
            #pragma unroll
            for (int jp=0; jp<4; jp++) {
                uint32_t bd = smem_u32 + (bbuf + (b_row + jp*16)*40 + k0 + b_kk)*2;
                LDM_X4(b[2*jp][0], b[2*jp][1], b[2*jp+1][0], b[2*jp+1][1], bd);
            }
            #pragma unroll
            for (int i=0;i<4;i++)
                #pragma unroll
                for (int j=0;j<8;j++) {
                    asm volatile(
                        "mma.sync.aligned.m16n8k16.row.col.f32.f16.f16.f32 "
                        "{%0,%1,%2,%3}, {%4,%5,%6,%7}, {%8,%9}, {%0,%1,%2,%3};"
                        : "+f"(acc[i][j][0]), "+f"(acc[i][j][1]),
                          "+f"(acc[i][j][2]), "+f"(acc[i][j][3])
                        : "r"(a[i][0]), "r"(a[i][1]), "r"(a[i][2]), "r"(a[i][3]),
                          "r"(b[j][0]), "r"(b[j][1]));
                }
        }
        __syncthreads();
    }

    #pragma unroll
    for (int i=0;i<4;i++) {
        int row0 = bm + wm64 + i*16 + qr;
        #pragma unroll
        for (int j=0;j<8;j++) {
            int col0 = bn + wn64 + j*8 + qc*2;
            float v0 = acc[i][j][0], v1 = acc[i][j][1];
            float v2 = acc[i][j][2], v3 = acc[i][j][3];
            if (BIASF) {
                float b0 = bias[col0], b1 = bias[col0+1];
                v0 += b0; v1 += b1; v2 += b0; v3 += b1;
            }
            if (ACT == 1) {
                v0 = 0.5f*v0*(1.f + erff(v0*0.70710678118654752f));
                v1 = 0.5f*v1*(1.f + erff(v1*0.70710678118654752f));
                v2 = 0.5f*v2*(1.f + erff(v2*0.70710678118654752f));
                v3 = 0.5f*v3*(1.f + erff(v3*0.70710678118654752f));
            }
            if (RESF) {
                v0 += res[(size_t)row0*N + col0];
                v1 += res[(size_t)row0*N + col0 + 1];
                v2 += res[(size_t)(row0+8)*N + col0];
                v3 += res[(size_t)(row0+8)*N + col0 + 1];
            }
            if (OUTHALF) {
                *(half2*)(Ch + (size_t)row0*N + col0)     = __floats2half2_rn(v0, v1);
                *(half2*)(Ch + (size_t)(row0+8)*N + col0) = __floats2half2_rn(v2, v3);
            } else {
                *(float2*)(Cf + (size_t)row0*N + col0)     = make_float2(v0, v1);
                *(float2*)(Cf + (size_t)(row0+8)*N + col0) = make_float2(v2, v3);
            }
        }
    }
}

// ---------------- legacy mma.sync tf32 GEMM (hidden weight-fold GEMMs) ----------
#define SMEM_FLOATS (4*4608)
#define A_OFFS(buf) ((buf)*4608)
#define B_OFFS(buf) (9216 + (buf)*4608)

template<int ACT, int BIASF, int RESF, int TF32OUT>
__global__ __launch_bounds__(256, 2) void gemm_tf32(
    const float* __restrict__ A, const float* __restrict__ B,
    const float* __restrict__ bias, const float* __restrict__ res,
    float* __restrict__ C, int M, int N, int K)
{
    extern __shared__ float sm[];
    const int tid = threadIdx.x;
    const int bm = blockIdx.y * 128;
    const int bn = blockIdx.x * 128;
    const int lane = tid & 31;
    const int warp = tid >> 5;
    const int wm64 = (warp & 1) * 64;
    const int wn32 = (warp >> 1) * 32;
    const int qr = lane >> 2;
    const int qc = lane & 3;
    uint32_t smem_u32 = (uint32_t)__cvta_generic_to_shared(sm);
    const int lrow = tid >> 3;
    const int lkq  = (tid & 7) * 4;

    float acc[4][4][4];
    #pragma unroll
    for (int i=0;i<4;i++)
        #pragma unroll
        for (int j=0;j<4;j++)
            #pragma unroll
            for (int e=0;e<4;e++) acc[i][j][e] = 0.f;

    const int NT = K >> 5;
    {
        const float* Ab = A + (size_t)bm*K;
        const float* Bb = B + (size_t)bn*K;
        #pragma unroll
        for (int rep=0; rep<4; rep++) {
            int row = rep*32 + lrow;
            cp16(smem_u32 + (A_OFFS(0) + row*36 + lkq)*4, Ab + (size_t)row*K + lkq);
            cp16(smem_u32 + (B_OFFS(0) + row*36 + lkq)*4, Bb + (size_t)row*K + lkq);
        }
        asm volatile("cp.async.commit_group;");
    }
    for (int t = 0; t < NT; t++) {
        if (t + 1 < NT) {
            int buf = (t+1) & 1;
            int kb = (t+1) << 5;
            const float* Ab = A + (size_t)bm*K + kb;
            const float* Bb = B + (size_t)bn*K + kb;
            #pragma unroll
            for (int rep=0; rep<4; rep++) {
                int row = rep*32 + lrow;
                cp16(smem_u32 + (A_OFFS(buf) + row*36 + lkq)*4, Ab + (size_t)row*K + lkq);
                cp16(smem_u32 + (B_OFFS(buf) + row*36 + lkq)*4, Bb + (size_t)row*K + lkq);
            }
            asm volatile("cp.async.commit_group;");
            asm volatile("cp.async.wait_group 1;");
        } else {
            asm volatile("cp.async.wait_group 0;");
        }
        __syncthreads();
        const float* sA = sm + A_OFFS(t & 1);
        const float* sB = sm + B_OFFS(t & 1);
        #pragma unroll
        for (int ks = 0; ks < 4; ks++) {
            const int k0 = ks * 8;
            uint32_t a[4][4], b[4][2];
            #pragma unroll
            for (int i=0;i<4;i++) {
                int r = wm64 + i*16 + qr;
                a[i][0] = __float_as_uint(sA[r*36 + k0 + qc]);
                a[i][1] = __float_as_uint(sA[(r+8)*36 + k0 + qc]);
                a[i][2] = __float_as_uint(sA[r*36 + k0 + qc + 4]);
                a[i][3] = __float_as_uint(sA[(r+8)*36 + k0 + qc + 4]);
            }
            #pragma unroll
            for (int j=0;j<4;j++) {
                int n = wn32 + j*8 + qr;
                b[j][0] = __float_as_uint(sB[n*36 + k0 + qc]);
                b[j][1] = __float_as_uint(sB[n*36 + k0 + qc + 4]);
            }
            #pragma unroll
            for (int i=0;i<4;i++)
                #pragma unroll
                for (int j=0;j<4;j++) {
                    asm volatile(
                        "mma.sync.aligned.m16n8k8.row.col.f32.tf32.tf32.f32 "
                        "{%0,%1,%2,%3}, {%4,%5,%6,%7}, {%8,%9}, {%0,%1,%2,%3};"
                        : "+f"(acc[i][j][0]), "+f"(acc[i][j][1]),
                          "+f"(acc[i][j][2]), "+f"(acc[i][j][3])
                        : "r"(a[i][0]), "r"(a[i][1]), "r"(a[i][2]), "r"(a[i][3]),
                          "r"(b[j][0]), "r"(b[j][1]));
                }
        }
        __syncthreads();
    }
    #pragma unroll
    for (int i=0;i<4;i++) {
        int row0 = bm + wm64 + i*16 + qr;
        #pragma unroll
        for (int j=0;j<4;j++) {
            int col0 = bn + wn32 + j*8 + qc*2;
            *(float2*)(C + (size_t)row0*N + col0)     = make_float2(acc[i][j][0], acc[i][j][1]);
            *(float2*)(C + (size_t)(row0+8)*N + col0) = make_float2(acc[i][j][2], acc[i][j][3]);
        }
    }
}

// ---------------- fp16 tensor-core flash self-attention -------------------------
#define KSH 24
#define VSH 1032
#define PSH 72
#define FLASH_SMEM ((1024*KSH + 16*VSH + 8*16*PSH)*2)

#define MMA_F16(acc, a, b0, b1) \
    asm volatile( \
        "mma.sync.aligned.m16n8k16.row.col.f32.f16.f16.f32 " \
        "{%0,%1,%2,%3}, {%4,%5,%6,%7}, {%8,%9}, {%0,%1,%2,%3};" \
        : "+f"((acc)[0]), "+f"((acc)[1]), "+f"((acc)[2]), "+f"((acc)[3]) \
        : "r"((a)[0]), "r"((a)[1]), "r"((a)[2]), "r"((a)[3]), \
          "r"(b0), "r"(b1))

__global__ __launch_bounds__(256) void flash_attn_kernel(
    const __half* __restrict__ qkv, __half* __restrict__ ao)
{
    extern __shared__ __half fsm[];
    __half* Ks = fsm;
    __half* Vs = fsm + 1024*KSH;
    __half* Ps = Vs + 16*VSH + (threadIdx.x >> 5)*16*PSH;

    const int b = blockIdx.x >> 6;
    const int h = blockIdx.x & 63;
    const int qt = blockIdx.y;
    const int tid = threadIdx.x;
    const int lane = tid & 31;
    const int warp = tid >> 5;
    const int qr = lane >> 2;
    const int qc = lane & 3;

    const __half* base = qkv + (size_t)b*T_SEQ*3*D + h*HD;

    for (int r = tid; r < T_SEQ; r += 256) {
        const uint32_t* kr = (const uint32_t*)(base + (size_t)r*3*D + D);
        #pragma unroll
        for (int i=0;i<8;i++) *(uint32_t*)(Ks + r*KSH + i*2) = kr[i];
        const __half* vr = base + (size_t)r*3*D + 2*D;
        #pragma unroll
        for (int d=0; d<16; d++) Vs[d*VSH + r] = vr[d];
    }

    const int q0 = qt*256 + warp*32;
    const half2 qs = __floats2half2_rn(0.25f, 0.25f);
    uint32_t aQ[2][4];
    #pragma unroll
    for (int mt=0; mt<2; mt++) {
        int r0 = q0 + mt*16 + qr;
        half2 v0 = __hmul2(*(const half2*)(base + (size_t)r0*3*D + 2*qc), qs);
        half2 v1 = __hmul2(*(const half2*)(base + (size_t)(r0+8)*3*D + 2*qc), qs);
        half2 v2 = __hmul2(*(const half2*)(base + (size_t)r0*3*D + 2*qc + 8), qs);
        half2 v3 = __hmul2(*(const half2*)(base + (size_t)(r0+8)*3*D + 2*qc + 8), qs);
        aQ[mt][0] = *(uint32_t*)&v0; aQ[mt][1] = *(uint32_t*)&v1;
        aQ[mt][2] = *(uint32_t*)&v2; aQ[mt][3] = *(uint32_t*)&v3;
    }
    __syncthreads();

    float mstate[2][2], lstate[2][2], oacc[2][2][4];
    #pragma unroll
    for (int mt=0; mt<2; mt++) {
        mstate[mt][0] = -1e30f; mstate[mt][1] = -1e30f;
        lstate[mt][0] = 0.f;    lstate[mt][1] = 0.f;
        #pragma unroll
        for (int nt=0; nt<2; nt++)
            #pragma unroll
            for (int e=0; e<4; e++) oacc[mt][nt][e] = 0.f;
    }

    for (int nc = 0; nc < 16; nc++) {
        const int kb = nc*64;
        #pragma unroll
        for (int mt=0; mt<2; mt++) {
            float sacc[8][4];
            #pragma unroll
            for (int nt=0; nt<8; nt++) {
                sacc[nt][0]=0.f; sacc[nt][1]=0.f; sacc[nt][2]=0.f; sacc[nt][3]=0.f;
                const int key = kb + nt*8 + qr;
                uint32_t b0 = *(const uint32_t*)(Ks + key*KSH + 2*qc);
                uint32_t b1 = *(const uint32_t*)(Ks + key*KSH + 2*qc + 8);
                MMA_F16(sacc[nt], aQ[mt], b0, b1);
            }
            float r0max = -1e30f, r1max = -1e30f;
            #pragma unroll
            for (int nt=0; nt<8; nt++) {
                r0max = fmaxf(r0max, fmaxf(sacc[nt][0], sacc[nt][1]));
                r1max = fmaxf(r1max, fmaxf(sacc[nt][2], sacc[nt][3]));
            }
            r0max = fmaxf(r0max, __shfl_xor_sync(0xFFFFFFFFu, r0max, 1));
            r0max = fmaxf(r0max, __shfl_xor_sync(0xFFFFFFFFu, r0max, 2));
            r1max = fmaxf(r1max, __shfl_xor_sync(0xFFFFFFFFu, r1max, 1));
            r1max = fmaxf(r1max, __shfl_xor_sync(0xFFFFFFFFu, r1max, 2));
            float mnew0 = fmaxf(mstate[mt][0], r0max);
            float mnew1 = fmaxf(mstate[mt][1], r1max);
            float corr0 = __expf(mstate[mt][0] - mnew0);
            float corr1 = __expf(mstate[mt][1] - mnew1);
            mstate[mt][0] = mnew0; mstate[mt][1] = mnew1;

            float rs0 = 0.f, rs1 = 0.f;
            #pragma unroll
            for (int nt=0; nt<8; nt++) {
                float p0 = __expf(sacc[nt][0] - mnew0);
                float p1 = __expf(sacc[nt][1] - mnew0);
                float p2 = __expf(sacc[nt][2] - mnew1);
                float p3 = __expf(sacc[nt][3] - mnew1);
                rs0 += p0 + p1; rs1 += p2 + p3;
                *(half2*)(Ps + qr*PSH + nt*8 + 2*qc)     = __floats2half2_rn(p0, p1);
                *(half2*)(Ps + (qr+8)*PSH + nt*8 + 2*qc) = __floats2half2_rn(p2, p3);
            }
            rs0 += __shfl_xor_sync(0xFFFFFFFFu, rs0, 1);
            rs0 += __shfl_xor_sync(0xFFFFFFFFu, rs0, 2);
            rs1 += __shfl_xor_sync(0xFFFFFFFFu, rs1, 1);
            rs1 += __shfl_xor_sync(0xFFFFFFFFu, rs1, 2);
            lstate[mt][0] = lstate[mt][0]*corr0 + rs0;
            lstate[mt][1] = lstate[mt][1]*corr1 + rs1;
            #pragma unroll
            for (int nt=0; nt<2; nt++) {
                oacc[mt][nt][0] *= corr0; oacc[mt][nt][1] *= corr0;
                oacc[mt][nt][2] *= corr1; oacc[mt][nt][3] *= corr1;
            }
            __syncwarp();
            #pragma unroll
            for (int ks=0; ks<4; ks++) {
                uint32_t a[4];
                a[0] = *(const uint32_t*)(Ps + qr*PSH + ks*16 + 2*qc);
                a[1] = *(const uint32_t*)(Ps + (qr+8)*PSH + ks*16 + 2*qc);
                a[2] = *(const uint32_t*)(Ps + qr*PSH + ks*16 + 2*qc + 8);
                a[3] = *(const uint32_t*)(Ps + (qr+8)*PSH + ks*16 + 2*qc + 8);
                #pragma unroll
                for (int nt=0; nt<2; nt++) {
                    const __half* vb = Vs + (nt*8+qr)*VSH + kb + ks*16;
                    uint32_t b0 = *(const uint32_t*)(vb + 2*qc);
                    uint32_t b1 = *(const uint32_t*)(vb + 2*qc + 8);
                    MMA_F16(oacc[mt][nt], a, b0, b1);
                }
            }
            __syncwarp();
        }
    }

    #pragma unroll
    for (int mt=0; mt<2; mt++) {
        float inv0 = 1.f/lstate[mt][0];
        float inv1 = 1.f/lstate[mt][1];
        int row0 = q0 + mt*16 + qr;
        #pragma unroll
        for (int nt=0; nt<2; nt++) {
            int col = h*HD + nt*8 + 2*qc;
            __half* o0 = ao + ((size_t)b*T_SEQ + row0)*D + col;
            __half* o1 = ao + ((size_t)b*T_SEQ + row0 + 8)*D + col;
            *(half2*)o0 = __floats2half2_rn(oacc[mt][nt][0]*inv0, oacc[mt][nt][1]*inv0);
            *(half2*)o1 = __floats2half2_rn(oacc[mt][nt][2]*inv1, oacc[mt][nt][3]*inv1);
        }
    }
}

// fold LN2 gamma into K' and compute per-slot constants:
// K''[row][d] = K'[row][d]*g2[d]; c1[row]=sum K''; c2[row]=sum beta2*K'
__global__ __launch_bounds__(128) void fold_kernel(
    const float* __restrict__ g2, const float* __restrict__ b2ln)
{
    __shared__ float s1[128], s2[128];
    int row = blockIdx.x;      // 0..63 (b*16+mm)
    float* kr = g_K + (size_t)row*D;
    float c1 = 0.f, c2 = 0.f;
    for (int d = threadIdx.x; d < D; d += 128) {
        float kv = kr[d];
        float kk = kv * g2[d];
        kr[d] = kk;
        c1 += kk;
        c2 += kv * b2ln[d];
    }
    s1[threadIdx.x] = c1; s2[threadIdx.x] = c2;
    __syncthreads();
    for (int off=64; off; off>>=1) {
        if (threadIdx.x < off) {
            s1[threadIdx.x]+=s1[threadIdx.x+off];
            s2[threadIdx.x]+=s2[threadIdx.x+off];
        }
        __syncthreads();
    }
    if (threadIdx.x == 0) {
        g_cc[row] = s1[0];
        g_cc[64 + row] = s2[0];
    }
}

// ---------------- cross-attention with fused LN2 --------------------------------
// scores[mm] = rstd * dot(x, K''[mm]) - rstd*mu*c1[mm] + c2[mm]; xo += softmax @ V'
__global__ __launch_bounds__(256) void cross_attn_kernel(
    const float* __restrict__ Km, const float* __restrict__ Vm,
    float* __restrict__ xo)
{
    extern __shared__ float csm[];
    float* Ks = csm;
    float* Vs = csm + NMEM*D;
    int b = blockIdx.x >> 2;
    int chunk = blockIdx.x & 3;
    for (int i=threadIdx.x; i<NMEM*D; i+=256) {
        Ks[i] = Km[(size_t)b*NMEM*D + i];
        Vs[i] = Vm[(size_t)b*NMEM*D + i];
    }
    __syncthreads();
    int t = chunk*256 + threadIdx.x;
    float* xrow = xo + ((size_t)b*T_SEQ + t)*D;
    const float4* qrow = (const float4*)xrow;
    float s[16];
    #pragma unroll
    for (int mm=0;mm<16;mm++) s[mm]=0.f;
    float sum = 0.f, sq = 0.f;
    for (int k4=0;k4<D/4;k4++) {
        float4 qv = qrow[k4];
        sum += qv.x+qv.y+qv.z+qv.w;
        sq  += qv.x*qv.x + qv.y*qv.y + qv.z*qv.z + qv.w*qv.w;
        #pragma unroll
        for (int mm=0;mm<16;mm++) {
            const float* kr = Ks + mm*D + k4*4;
            s[mm] += qv.x*kr[0] + qv.y*kr[1] + qv.z*kr[2] + qv.w*kr[3];
        }
    }
    float mu = sum*(1.0f/D);
    float var = sq*(1.0f/D) - mu*mu;
    float rstd = rsqrtf(var + 1e-5f);
    float mx = -1e30f;
    #pragma unroll
    for (int mm=0;mm<16;mm++) {
        s[mm] = (rstd*s[mm] - rstd*mu*g_cc[b*16+mm] + g_cc[64 + b*16+mm]) * 0.03125f;
        mx = fmaxf(mx, s[mm]);
    }
    float ssum = 0.f;
    #pragma unroll
    for (int mm=0;mm<16;mm++) { s[mm] = __expf(s[mm]-mx); ssum += s[mm]; }
    float inv = 1.f/ssum;
    #pragma unroll
    for (int mm=0;mm<16;mm++) s[mm] *= inv;
    for (int c=0;c<D;c+=4) {
        float4 o = *(const float4*)(xrow + c);
        #pragma unroll
        for (int mm=0;mm<16;mm++) {
            const float* vr = Vs + mm*D + c;
            o.x += s[mm]*vr[0]; o.y += s[mm]*vr[1];
            o.z += s[mm]*vr[2]; o.w += s[mm]*vr[3];
        }
        *(float4*)(xrow + c) = o;
    }
}

// ---------------- memory path -------------------------------------------------
__global__ __launch_bounds__(256) void mean_kernel(const float* __restrict__ x,
                                                   float* __restrict__ mh) {
    __shared__ float sred[256];
    int b = blockIdx.x, cb = blockIdx.y*128;
    int c = threadIdx.x & 127, half = threadIdx.x >> 7;
    const float* p = x + (size_t)b*T_SEQ*D + (size_t)half*512*D + cb + c;
    float s = 0.f;
    #pragma unroll 4
    for (int t=0;t<512;t++) s += p[(size_t)t*D];
    sred[threadIdx.x] = s;
    __syncthreads();
    if (half == 0)
        mh[b*D + cb + c] = (sred[threadIdx.x] + sred[threadIdx.x+128]) * (1.f/T_SEQ);
}

__global__ __launch_bounds__(256) void base_gemv(
    const float* __restrict__ Wz, const float* __restrict__ Wr, const float* __restrict__ Wc,
    const float* __restrict__ bz, const float* __restrict__ br, const float* __restrict__ bc)
{
    int gid = blockIdx.x*8 + (threadIdx.x >> 5);
    int lane = threadIdx.x & 31;
    int g = gid >> 12;
    int rem = gid & 4095;
    int b = rem >> 10;
    int col = rem & 1023;
    const float* W    = (g==0) ? Wz : ((g==1) ? Wr : Wc);
    const float* bias = (g==0) ? bz : ((g==1) ? br : bc);
    const float* wrow = W + (size_t)col*2048;
    const float* mrow = g_meanh + b*D;
    float acc = 0.f;
    #pragma unroll
    for (int k0=0;k0<1024;k0+=128) {
        float4 w = *(const float4*)(wrow + k0 + lane*4);
        float4 m = *(const float4*)(mrow + k0 + lane*4);
        acc += w.x*m.x + w.y*m.y + w.z*m.z + w.w*m.w;
    }
    #pragma unroll
    for (int o=16;o;o>>=1) acc += __shfl_xor_sync(0xFFFFFFFFu, acc, o);
    if (lane == 0) g_base[gid] = acc + bias[col];
}

__device__ __forceinline__ void tile64x64(
    const float* __restrict__ A, const float* __restrict__ B, int ldb,
    float (&acc)[4][4])
{
    __shared__ float As[32][65];
    __shared__ float Bs[32][65];
    const int tid = threadIdx.x;
    const int r  = tid >> 2;
    const int kq = (tid & 3) << 3;
    const int tx = tid & 15;
    const int ty = tid >> 4;
    for (int k0 = 0; k0 < 1024; k0 += 32) {
        float4 a0 = *(const float4*)(A + (size_t)r*1024 + k0 + kq);
        float4 a1 = *(const float4*)(A + (size_t)r*1024 + k0 + kq + 4);
        float4 b0 = *(const float4*)(B + (size_t)r*ldb  + k0 + kq);
        float4 b1 = *(const float4*)(B + (size_t)r*ldb  + k0 + kq + 4);
        __syncthreads();
        As[kq+0][r]=a0.x; As[kq+1][r]=a0.y; As[kq+2][r]=a0.z; As[kq+3][r]=a0.w;
        As[kq+4][r]=a1.x; As[kq+5][r]=a1.y; As[kq+6][r]=a1.z; As[kq+7][r]=a1.w;
        Bs[kq+0][r]=b0.x; Bs[kq+1][r]=b0.y; Bs[kq+2][r]=b0.z; Bs[kq+3][r]=b0.w;
        Bs[kq+4][r]=b1.x; Bs[kq+5][r]=b1.y; Bs[kq+6][r]=b1.z; Bs[kq+7][r]=b1.w;
        __syncthreads();
        #pragma unroll
        for (int kk=0;kk<32;kk++) {
            float a[4], b[4];
            #pragma unroll
            for (int i=0;i<4;i++) a[i] = As[kk][ty*4+i];
            #pragma unroll
            for (int j=0;j<4;j++) b[j] = Bs[kk][tx*4+j];
            #pragma unroll
            for (int i=0;i<4;i++)
                #pragma unroll
                for (int j=0;j<4;j++) acc[i][j] += a[i]*b[j];
        }
    }
}

__global__ __launch_bounds__(256) void zr_pre(
    const float* __restrict__ mem, const float* __restrict__ Wz,
    const float* __restrict__ Wr)
{
    int g = blockIdx.y;
    int ct = blockIdx.x;
    const float* W = (g ? Wr : Wz) + (size_t)(ct*64)*2048 + 1024;
    float acc[4][4];
    #pragma unroll
    for (int i=0;i<4;i++)
        #pragma unroll
        for (int j=0;j<4;j++) acc[i][j]=0.f;
    tile64x64(mem, W, 2048, acc);
    float* out = g ? g_rpre : g_zpre;
    const int tx = threadIdx.x & 15, ty = threadIdx.x >> 4;
    #pragma unroll
    for (int i=0;i<4;i++) {
        int row = ty*4+i;
        #pragma unroll
        for (int j=0;j<4;j++) out[row*1024 + ct*64 + tx*4+j] = acc[i][j];
    }
}

__global__ void combine_kernel(const float* __restrict__ mem) {
    int idx = blockIdx.x*blockDim.x + threadIdx.x;
    int row = idx >> 10, col = idx & 1023, b = row >> 4;
    float z = 1.f/(1.f + __expf(-(g_zpre[idx] + g_base[0*4096 + b*1024 + col])));
    float r = 1.f/(1.f + __expf(-(g_rpre[idx] + g_base[1*4096 + b*1024 + col])));
    g_z[idx] = z;
    g_rm[idx] = r * mem[idx];
}

__global__ __launch_bounds__(256) void c_gemm(
    const float* __restrict__ mem, const float* __restrict__ Wc,
    float* __restrict__ newmem)
{
    int ct = blockIdx.x;
    const float* W = Wc + (size_t)(ct*64)*2048 + 1024;
    float acc[4][4];
    #pragma unroll
    for (int i=0;i<4;i++)
        #pragma unroll
        for (int j=0;j<4;j++) acc[i][j]=0.f;
    tile64x64(g_rm, W, 2048, acc);
    const int tx = threadIdx.x & 15, ty = threadIdx.x >> 4;
    #pragma unroll
    for (int i=0;i<4;i++) {
        int row = ty*4+i;
        #pragma unroll
        for (int j=0;j<4;j++) {
            int col = ct*64 + tx*4+j;
            float v = acc[i][j] + g_base[2*4096 + (row>>4)*1024 + col];
            float c = tanhf(v);
            float z = g_z[row*1024+col];
            newmem[(size_t)row*1024+col] = (1.f - z)*mem[(size_t)row*1024+col] + z*c;
        }
    }
}

__global__ __launch_bounds__(256) void kv2_gemm(const float* __restrict__ newmem)
{
    int which = blockIdx.y;
    int ct = blockIdx.x;
    const float* W = (which ? g_wv : g_wk) + (size_t)(ct*64)*1024;
    float acc[4][4];
    #pragma unroll
    for (int i=0;i<4;i++)
        #pragma unroll
        for (int j=0;j<4;j++) acc[i][j]=0.f;
    tile64x64(newmem, W, 1024, acc);
    float* out = which ? g_V : g_K;
    const int tx = threadIdx.x & 15, ty = threadIdx.x >> 4;
    #pragma unroll
    for (int i=0;i<4;i++) {
        int row = ty*4+i;
        #pragma unroll
        for (int j=0;j<4;j++) {
            int col = ct*64 + tx*4+j;
            out[(size_t)row*1024+col] = acc[i][j];
        }
    }
}

// ---------------- host launcher -------------------------------------------------
extern "C" void kernel_launch(void* const* d_in, const int* in_sizes, int n_in,
                              void* d_out, int out_size)
{
    const float* x          = (const float*)d_in[0];
    const float* memory     = (const float*)d_in[1];
    const float* ln1_g      = (const float*)d_in[2];
    const float* ln1_b      = (const float*)d_in[3];
    const float* ln2_g      = (const float*)d_in[4];
    const float* ln2_b      = (const float*)d_in[5];
    const float* ln3_g      = (const float*)d_in[6];
    const float* ln3_b      = (const float*)d_in[7];
    const float* in_proj_w  = (const float*)d_in[8];
    const float* in_proj_b  = (const float*)d_in[9];
    const float* attn_out_w = (const float*)d_in[10];
    const float* attn_out_b = (const float*)d_in[11];
    const float* Wz_w       = (const float*)d_in[12];
    const float* Wz_b       = (const float*)d_in[13];
    const float* Wr_w       = (const float*)d_in[14];
    const float* Wr_b       = (const float*)d_in[15];
    const float* Wc_w       = (const float*)d_in[16];
    const float* Wc_b       = (const float*)d_in[17];
    const float* mq_w       = (const float*)d_in[18];
    const float* mk_w       = (const float*)d_in[19];
    const float* mv_w       = (const float*)d_in[20];
    const float* mo_w       = (const float*)d_in[21];
    const float* W1         = (const float*)d_in[22];
    const float* b1         = (const float*)d_in[23];
    const float* W2         = (const float*)d_in[24];
    const float* b2         = (const float*)d_in[25];

    float* xo = (float*)d_out;
    float* newmem = xo + (size_t)ROWS*D;

    float *p_K, *p_V, *p_w, *p_mh, *p_wk, *p_wv;
    __half *p_hh, *p_hqkv, *p_hao, *p_hffn, *p_hw;
    cudaGetSymbolAddress((void**)&p_K,    g_K);
    cudaGetSymbolAddress((void**)&p_V,    g_V);
    cudaGetSymbolAddress((void**)&p_w,    g_w);
    cudaGetSymbolAddress((void**)&p_mh,   g_meanh);
    cudaGetSymbolAddress((void**)&p_wk,   g_wk);
    cudaGetSymbolAddress((void**)&p_wv,   g_wv);
    cudaGetSymbolAddress((void**)&p_hh,   h_h);
    cudaGetSymbolAddress((void**)&p_hqkv, h_qkv);
    cudaGetSymbolAddress((void**)&p_hao,  h_ao);
    cudaGetSymbolAddress((void**)&p_hffn, h_ffn);
    cudaGetSymbolAddress((void**)&p_hw,   h_w);

    static cudaStream_t s2 = nullptr;
    static cudaEvent_t evStart = nullptr, evCvt = nullptr, evFork = nullptr, evMem = nullptr;
    static bool tried = false, ok = false;
    if (!tried) {
        tried = true;
        ok = (cudaStreamCreateWithFlags(&s2, cudaStreamNonBlocking) == cudaSuccess) &&
             (cudaEventCreateWithFlags(&evStart, cudaEventDisableTiming) == cudaSuccess) &&
             (cudaEventCreateWithFlags(&evCvt,   cudaEventDisableTiming) == cudaSuccess) &&
             (cudaEventCreateWithFlags(&evFork,  cudaEventDisableTiming) == cudaSuccess) &&
             (cudaEventCreateWithFlags(&evMem,   cudaEventDisableTiming) == cudaSuccess);
    }
    cudaStream_t sb = ok ? s2 : (cudaStream_t)0;

    cudaFuncSetAttribute(flash_attn_kernel, cudaFuncAttributeMaxDynamicSharedMemorySize, FLASH_SMEM);
    cudaFuncSetAttribute(cross_attn_kernel, cudaFuncAttributeMaxDynamicSharedMemorySize, 131072);
    const int GSM = SMEM_FLOATS * 4;
    cudaFuncSetAttribute(gemm_tf32<0,0,0,0>, cudaFuncAttributeMaxDynamicSharedMemorySize, GSM);
    cudaFuncSetAttribute(gemm_fp16<0,1,0,1>, cudaFuncAttributeMaxDynamicSharedMemorySize, HSMEM_BYTES);
    cudaFuncSetAttribute(gemm_fp16<0,1,1,0>, cudaFuncAttributeMaxDynamicSharedMemorySize, HSMEM_BYTES);
    cudaFuncSetAttribute(gemm_fp16<1,1,0,1>, cudaFuncAttributeMaxDynamicSharedMemorySize, HSMEM_BYTES);

    // ---- early hidden phase on sb ----
    if (ok) { cudaEventRecord(evStart, 0); cudaStreamWaitEvent(sb, evStart, 0); }
    cvt_fp16_kernel<<<3072, 256, 0, sb>>>(in_proj_w,  p_hw + HOFF_INP,  3*1024*1024/4);
    cvt_fp16_kernel<<<1024, 256, 0, sb>>>(attn_out_w, p_hw + HOFF_AOUT, 1024*1024/4);
    cvt_fp16_kernel<<<4096, 256, 0, sb>>>(W1,         p_hw + HOFF_W1,   4*1024*1024/4);
    cvt_fp16_kernel<<<4096, 256, 0, sb>>>(W2,         p_hw + HOFF_W2,   4*1024*1024/4);
    if (ok) cudaEventRecord(evCvt, sb);
    cvt_tf32_kernel<<<1024, 256, 0, sb>>>(mo_w, p_w + OFF_MO, 1024*1024/4);
    transpose_tf32<<<dim3(32,32), dim3(32,8), 0, sb>>>(mq_w, p_w + OFF_MQT);
    transpose_tf32<<<dim3(32,32), dim3(32,8), 0, sb>>>(mk_w, p_w + OFF_MKT);
    transpose_tf32<<<dim3(32,32), dim3(32,8), 0, sb>>>(mv_w, p_w + OFF_MVT);
    gemm_tf32<0,0,0,0><<<dim3(8,8), 256, GSM, sb>>>(p_w + OFF_MQT, p_w + OFF_MKT, nullptr, nullptr, p_wk, 1024, 1024, 1024);
    gemm_tf32<0,0,0,0><<<dim3(8,8), 256, GSM, sb>>>(p_w + OFF_MO,  p_w + OFF_MVT, nullptr, nullptr, p_wv, 1024, 1024, 1024);
    zr_pre<<<dim3(16,2), 256, 0, sb>>>(memory, Wz_w, Wr_w);

    // ---- main path ----
    ln_kernel_h<<<ROWS, 256>>>(x, ln1_g, ln1_b, p_hh);
    if (ok) cudaStreamWaitEvent(0, evCvt, 0);

    gemm_fp16<0,1,0,1><<<dim3(3*D/128, ROWS/128), 128, HSMEM_BYTES>>>(p_hh, p_hw + HOFF_INP, in_proj_b, nullptr, p_hqkv, ROWS, 3*D, D);
    flash_attn_kernel<<<dim3(BATCH*NHEADS, 4), 256, FLASH_SMEM>>>(p_hqkv, p_hao);
    gemm_fp16<0,1,1,0><<<dim3(D/128, ROWS/128), 128, HSMEM_BYTES>>>(p_hao, p_hw + HOFF_AOUT, attn_out_b, x, xo, ROWS, D, D);

    // ---- fork memory path onto sb ----
    if (ok) { cudaEventRecord(evFork, 0); cudaStreamWaitEvent(sb, evFork, 0); }
    mean_kernel<<<dim3(BATCH, 8), 256, 0, sb>>>(xo, p_mh);
    base_gemv<<<1536, 256, 0, sb>>>(Wz_w, Wr_w, Wc_w, Wz_b, Wr_b, Wc_b);
    combine_kernel<<<BATCH*NMEM*D/256, 256, 0, sb>>>(memory);
    c_gemm<<<16, 256, 0, sb>>>(memory, Wc_w, newmem);
    kv2_gemm<<<dim3(16, 2), 256, 0, sb>>>(newmem);
    fold_kernel<<<BATCH*NMEM, 128, 0, sb>>>(ln2_g, ln2_b);
    if (ok) cudaEventRecord(evMem, sb);

    // ---- main path: fused LN2 + cross-attention (in-place residual) ----
    if (ok) cudaStreamWaitEvent(0, evMem, 0);
    cross_attn_kernel<<<BATCH*4, 256, 131072>>>(p_K, p_V, xo);

    // FFN
    ln_kernel_h<<<ROWS, 256>>>(xo, ln3_g, ln3_b, p_hh);
    gemm_fp16<1,1,0,1><<<dim3(4*D/128, ROWS/128), 128, HSMEM_BYTES>>>(p_hh, p_hw + HOFF_W1, b1, nullptr, p_hffn, ROWS, 4*D, D);
    gemm_fp16<0,1,1,0><<<dim3(D/128, ROWS/128), 128, HSMEM_BYTES>>>(p_hffn, p_hw + HOFF_W2, b2, xo, xo, ROWS, D, 4*D);
}

// round 15
// speedup vs baseline: 1.0169x; 1.0169x over previous
#include <cuda_runtime.h>
#include <cuda_fp16.h>
#include <math.h>
#include <stdint.h>

#define D 1024
#define T_SEQ 1024
#define BATCH 4
#define NMEM 16
#define NHEADS 64
#define HD 16
#define ROWS (BATCH*T_SEQ)   // 4096

// ---------------- scratch (device globals; no runtime allocation) ----------------
__device__ __half h_h[ROWS*D];           // LN1/LN3 outputs (fp16)
__device__ __half h_qkv[ROWS*3*D];       // QKV (fp16)
__device__ __half h_ao[ROWS*D];          // self-attention output (fp16)
__device__ __half h_ffn[ROWS*4*D];       // FFN hidden (fp16)
__device__ float g_meanh[BATCH*D];
__device__ float g_base[3*BATCH*D];
__device__ float g_zpre[BATCH*NMEM*D];
__device__ float g_rpre[BATCH*NMEM*D];
__device__ float g_z[BATCH*NMEM*D];
__device__ float g_rm[BATCH*NMEM*D];
__device__ float g_K[BATCH*NMEM*D];      // K' -> K'' = g2 * K' (folded in place)
__device__ float g_V[BATCH*NMEM*D];
__device__ float g_cc[2*BATCH*NMEM];     // c1 = sum(K''), c2 = sum(beta2*K')
__device__ float g_wk[1024*1024];        // Wk' = mq^T @ mk
__device__ float g_wv[1024*1024];        // Wv' = mo @ mv
__device__ float g_w[8*1024*1024];       // float scratch for fold path
__device__ __half h_w[12*1024*1024];     // fp16 weight copies

#define OFF_MQT   0
#define OFF_MO    (1*1024*1024)
#define OFF_MKT   (2*1024*1024)
#define OFF_MVT   (3*1024*1024)
#define HOFF_INP  0
#define HOFF_AOUT (3*1024*1024)
#define HOFF_W1   (4*1024*1024)
#define HOFF_W2   (8*1024*1024)

__device__ __forceinline__ float to_tf32(float v) {
    uint32_t r;
    asm("cvt.rna.tf32.f32 %0, %1;" : "=r"(r) : "f"(v));
    return __uint_as_float(r);
}

// ---------------- utility kernels ----------------
__global__ void cvt_tf32_kernel(const float* __restrict__ src, float* __restrict__ dst, int n4) {
    int i = blockIdx.x*blockDim.x + threadIdx.x;
    if (i < n4) {
        float4 v = ((const float4*)src)[i];
        v.x = to_tf32(v.x); v.y = to_tf32(v.y); v.z = to_tf32(v.z); v.w = to_tf32(v.w);
        ((float4*)dst)[i] = v;
    }
}

__global__ void cvt_fp16_kernel(const float* __restrict__ src, __half* __restrict__ dst, int n4) {
    int i = blockIdx.x*blockDim.x + threadIdx.x;
    if (i < n4) {
        float4 v = ((const float4*)src)[i];
        half2 lo = __floats2half2_rn(v.x, v.y);
        half2 hi = __floats2half2_rn(v.z, v.w);
        ((half2*)dst)[2*i]   = lo;
        ((half2*)dst)[2*i+1] = hi;
    }
}

__global__ __launch_bounds__(256) void transpose_tf32(
    const float* __restrict__ src, float* __restrict__ dst)
{
    __shared__ float tile[32][33];
    int x = blockIdx.x*32 + threadIdx.x;
    int y0 = blockIdx.y*32 + threadIdx.y;
    #pragma unroll
    for (int i=0;i<32;i+=8)
        tile[threadIdx.y+i][threadIdx.x] = src[(size_t)(y0+i)*1024 + x];
    __syncthreads();
    int x2 = blockIdx.y*32 + threadIdx.x;
    int y2 = blockIdx.x*32 + threadIdx.y;
    #pragma unroll
    for (int i=0;i<32;i+=8)
        dst[(size_t)(y2+i)*1024 + x2] = to_tf32(tile[threadIdx.x][threadIdx.y+i]);
}

__global__ __launch_bounds__(256) void ln_kernel_h(
    const float* __restrict__ x, const float* __restrict__ g,
    const float* __restrict__ b, __half* __restrict__ y)
{
    __shared__ float s1[256], s2[256];
    int row = blockIdx.x;
    const float4* xr = (const float4*)(x + (size_t)row*D);
    float4 v = xr[threadIdx.x];
    float sum = v.x+v.y+v.z+v.w;
    float sq  = v.x*v.x + v.y*v.y + v.z*v.z + v.w*v.w;
    s1[threadIdx.x]=sum; s2[threadIdx.x]=sq;
    __syncthreads();
    for (int off=128; off; off>>=1) {
        if (threadIdx.x < off) {
            s1[threadIdx.x]+=s1[threadIdx.x+off];
            s2[threadIdx.x]+=s2[threadIdx.x+off];
        }
        __syncthreads();
    }
    float mean = s1[0]*(1.0f/D);
    float var  = s2[0]*(1.0f/D) - mean*mean;
    float rstd = rsqrtf(var + 1e-5f);
    int c = threadIdx.x*4;
    float4 gg = *(const float4*)(g+c);
    float4 bb = *(const float4*)(b+c);
    half2 lo = __floats2half2_rn((v.x-mean)*rstd*gg.x + bb.x, (v.y-mean)*rstd*gg.y + bb.y);
    half2 hi = __floats2half2_rn((v.z-mean)*rstd*gg.z + bb.z, (v.w-mean)*rstd*gg.w + bb.w);
    half2* yr = (half2*)(y + (size_t)row*D);
    yr[threadIdx.x*2]   = lo;
    yr[threadIdx.x*2+1] = hi;
}

__device__ __forceinline__ void cp16(uint32_t dst, const void* src) {
    asm volatile("cp.async.cg.shared.global [%0], [%1], 16;" :: "r"(dst), "l"(src));
}

#define LDM_X4(r0, r1, r2, r3, addr) \
    asm volatile("ldmatrix.sync.aligned.m8n8.x4.shared.b16 {%0,%1,%2,%3}, [%4];" \
        : "=r"(r0), "=r"(r1), "=r"(r2), "=r"(r3) : "r"(addr))

// ---------------- fp16 tensor-core GEMM: C(M,N) = A(M,K) @ B(N,K)^T -------------
// m16n8k16 HMMA, fp32 accum. 128x128 block, 8 warps (256 thr), 64x32 warp tile,
// BK=32, 4-stage cp.async ring, ldmatrix fragments.  (round-13 measured-best)
#define HA_OFF(buf) ((buf)*10240)
#define HB_OFF(buf) (5120 + (buf)*10240)
#define HSMEM_BYTES (4*10240*2)   // 81920 B

template<int ACT, int BIASF, int RESF, int OUTHALF>
__global__ __launch_bounds__(256, 2) void gemm_fp16(
    const __half* __restrict__ A, const __half* __restrict__ B,
    const float* __restrict__ bias, const float* __restrict__ res,
    void* __restrict__ Cv, int M, int N, int K)
{
    extern __shared__ __half hsm[];
    float* Cf = (float*)Cv;
    __half* Ch = (__half*)Cv;
    const int tid = threadIdx.x;
    const int bm = blockIdx.y * 128;
    const int bn = blockIdx.x * 128;
    const int lane = tid & 31;
    const int warp = tid >> 5;
    const int wm64 = (warp & 1) * 64;
    const int wn32 = (warp >> 1) * 32;
    const int qr = lane >> 2;
    const int qc = lane & 3;
    uint32_t smem_u32 = (uint32_t)__cvta_generic_to_shared(hsm);

    const int a_row = wm64 + (lane & 7) + ((lane >> 3) & 1) * 8;  // + i*16
    const int a_kk  = (lane >> 4) * 8;
    const int b_row = wn32 + (lane & 7) + ((lane >= 16) ? 8 : 0); // + jp*16
    const int b_kk  = ((lane >> 3) & 1) * 8;

    const int ld_row = tid >> 2;        // 0..63 (+64 per rep)
    const int ld_seg = (tid & 3) * 8;   // halves

    float acc[4][4][4];
    #pragma unroll
    for (int i=0;i<4;i++)
        #pragma unroll
        for (int j=0;j<4;j++)
            #pragma unroll
            for (int e=0;e<4;e++) acc[i][j][e] = 0.f;

    const int NT = K >> 5;

    // prologue: prefetch stages 0..2
    #pragma unroll
    for (int p=0; p<3; p++) {
        const __half* Ab = A + (size_t)bm*K + p*32;
        const __half* Bb = B + (size_t)bn*K + p*32;
        #pragma unroll
        for (int rep=0; rep<2; rep++) {
            int row = rep*64 + ld_row;
            cp16(smem_u32 + (HA_OFF(p) + row*40 + ld_seg)*2, Ab + (size_t)row*K + ld_seg);
            cp16(smem_u32 + (HB_OFF(p) + row*40 + ld_seg)*2, Bb + (size_t)row*K + ld_seg);
        }
        asm volatile("cp.async.commit_group;");
    }

    for (int t = 0; t < NT; t++) {
        if (t + 3 <= NT)      asm volatile("cp.async.wait_group 2;");
        else if (t + 2 == NT) asm volatile("cp.async.wait_group 1;");
        else                  asm volatile("cp.async.wait_group 0;");
        __syncthreads();

        if (t + 3 < NT) {
            int buf = (t+3) & 3;
            int kb = (t+3) << 5;
            const __half* Ab = A + (size_t)bm*K + kb;
            const __half* Bb = B + (size_t)bn*K + kb;
            #pragma unroll
            for (int rep=0; rep<2; rep++) {
                int row = rep*64 + ld_row;
                cp16(smem_u32 + (HA_OFF(buf) + row*40 + ld_seg)*2, Ab + (size_t)row*K + ld_seg);
                cp16(smem_u32 + (HB_OFF(buf) + row*40 + ld_seg)*2, Bb + (size_t)row*K + ld_seg);
            }
            asm volatile("cp.async.commit_group;");
        }

        const uint32_t abuf = HA_OFF(t & 3);
        const uint32_t bbuf = HB_OFF(t & 3);

        #pragma unroll
        for (int ks = 0; ks < 2; ks++) {
            const int k0 = ks * 16;
            uint32_t a[4][4], b[4][2];
            #pragma unroll
            for (int i=0;i<4;i++) {
                uint32_t ad = smem_u32 + (abuf + (a_row + i*16)*40 + k0 + a_kk)*2;
                LDM_X4(a[i][0], a[i][1], a[i][2], a[i][3], ad);
            }
            #pragma unroll
            for (int jp=0; jp<2; jp++) {
                uint32_t bd = smem_u32 + (bbuf + (b_row + jp*16)*40 + k0 + b_kk)*2;
                LDM_X4(b[2*jp][0], b[2*jp][1], b[2*jp+1][0], b[2*jp+1][1], bd);
            }
            #pragma unroll
            for (int i=0;i<4;i++)
                #pragma unroll
                for (int j=0;j<4;j++) {
                    asm volatile(
                        "mma.sync.aligned.m16n8k16.row.col.f32.f16.f16.f32 "
                        "{%0,%1,%2,%3}, {%4,%5,%6,%7}, {%8,%9}, {%0,%1,%2,%3};"
                        : "+f"(acc[i][j][0]), "+f"(acc[i][j][1]),
                          "+f"(acc[i][j][2]), "+f"(acc[i][j][3])
                        : "r"(a[i][0]), "r"(a[i][1]), "r"(a[i][2]), "r"(a[i][3]),
                          "r"(b[j][0]), "r"(b[j][1]));
                }
        }
        __syncthreads();
    }

    #pragma unroll
    for (int i=0;i<4;i++) {
        int row0 = bm + wm64 + i*16 + qr;
        #pragma unroll
        for (int j=0;j<4;j++) {
            int col0 = bn + wn32 + j*8 + qc*2;
            float v0 = acc[i][j][0], v1 = acc[i][j][1];
            float v2 = acc[i][j][2], v3 = acc[i][j][3];
            if (BIASF) {
                float b0 = bias[col0], b1 = bias[col0+1];
                v0 += b0; v1 += b1; v2 += b0; v3 += b1;
            }
            if (ACT == 1) {
                v0 = 0.5f*v0*(1.f + erff(v0*0.70710678118654752f));
                v1 = 0.5f*v1*(1.f + erff(v1*0.70710678118654752f));
                v2 = 0.5f*v2*(1.f + erff(v2*0.70710678118654752f));
                v3 = 0.5f*v3*(1.f + erff(v3*0.70710678118654752f));
            }
            if (RESF) {
                v0 += res[(size_t)row0*N + col0];
                v1 += res[(size_t)row0*N + col0 + 1];
                v2 += res[(size_t)(row0+8)*N + col0];
                v3 += res[(size_t)(row0+8)*N + col0 + 1];
            }
            if (OUTHALF) {
                *(half2*)(Ch + (size_t)row0*N + col0)     = __floats2half2_rn(v0, v1);
                *(half2*)(Ch + (size_t)(row0+8)*N + col0) = __floats2half2_rn(v2, v3);
            } else {
                *(float2*)(Cf + (size_t)row0*N + col0)     = make_float2(v0, v1);
                *(float2*)(Cf + (size_t)(row0+8)*N + col0) = make_float2(v2, v3);
            }
        }
    }
}

// ---------------- legacy mma.sync tf32 GEMM (hidden weight-fold GEMMs) ----------
#define SMEM_FLOATS (4*4608)
#define A_OFFS(buf) ((buf)*4608)
#define B_OFFS(buf) (9216 + (buf)*4608)

template<int ACT, int BIASF, int RESF, int TF32OUT>
__global__ __launch_bounds__(256, 2) void gemm_tf32(
    const float* __restrict__ A, const float* __restrict__ B,
    const float* __restrict__ bias, const float* __restrict__ res,
    float* __restrict__ C, int M, int N, int K)
{
    extern __shared__ float sm[];
    const int tid = threadIdx.x;
    const int bm = blockIdx.y * 128;
    const int bn = blockIdx.x * 128;
    const int lane = tid & 31;
    const int warp = tid >> 5;
    const int wm64 = (warp & 1) * 64;
    const int wn32 = (warp >> 1) * 32;
    const int qr = lane >> 2;
    const int qc = lane & 3;
    uint32_t smem_u32 = (uint32_t)__cvta_generic_to_shared(sm);
    const int lrow = tid >> 3;
    const int lkq  = (tid & 7) * 4;

    float acc[4][4][4];
    #pragma unroll
    for (int i=0;i<4;i++)
        #pragma unroll
        for (int j=0;j<4;j++)
            #pragma unroll
            for (int e=0;e<4;e++) acc[i][j][e] = 0.f;

    const int NT = K >> 5;
    {
        const float* Ab = A + (size_t)bm*K;
        const float* Bb = B + (size_t)bn*K;
        #pragma unroll
        for (int rep=0; rep<4; rep++) {
            int row = rep*32 + lrow;
            cp16(smem_u32 + (A_OFFS(0) + row*36 + lkq)*4, Ab + (size_t)row*K + lkq);
            cp16(smem_u32 + (B_OFFS(0) + row*36 + lkq)*4, Bb + (size_t)row*K + lkq);
        }
        asm volatile("cp.async.commit_group;");
    }
    for (int t = 0; t < NT; t++) {
        if (t + 1 < NT) {
            int buf = (t+1) & 1;
            int kb = (t+1) << 5;
            const float* Ab = A + (size_t)bm*K + kb;
            const float* Bb = B + (size_t)bn*K + kb;
            #pragma unroll
            for (int rep=0; rep<4; rep++) {
                int row = rep*32 + lrow;
                cp16(smem_u32 + (A_OFFS(buf) + row*36 + lkq)*4, Ab + (size_t)row*K + lkq);
                cp16(smem_u32 + (B_OFFS(buf) + row*36 + lkq)*4, Bb + (size_t)row*K + lkq);
            }
            asm volatile("cp.async.commit_group;");
            asm volatile("cp.async.wait_group 1;");
        } else {
            asm volatile("cp.async.wait_group 0;");
        }
        __syncthreads();
        const float* sA = sm + A_OFFS(t & 1);
        const float* sB = sm + B_OFFS(t & 1);
        #pragma unroll
        for (int ks = 0; ks < 4; ks++) {
            const int k0 = ks * 8;
            uint32_t a[4][4], b[4][2];
            #pragma unroll
            for (int i=0;i<4;i++) {
                int r = wm64 + i*16 + qr;
                a[i][0] = __float_as_uint(sA[r*36 + k0 + qc]);
                a[i][1] = __float_as_uint(sA[(r+8)*36 + k0 + qc]);
                a[i][2] = __float_as_uint(sA[r*36 + k0 + qc + 4]);
                a[i][3] = __float_as_uint(sA[(r+8)*36 + k0 + qc + 4]);
            }
            #pragma unroll
            for (int j=0;j<4;j++) {
                int n = wn32 + j*8 + qr;
                b[j][0] = __float_as_uint(sB[n*36 + k0 + qc]);
                b[j][1] = __float_as_uint(sB[n*36 + k0 + qc + 4]);
            }
            #pragma unroll
            for (int i=0;i<4;i++)
                #pragma unroll
                for (int j=0;j<4;j++) {
                    asm volatile(
                        "mma.sync.aligned.m16n8k8.row.col.f32.tf32.tf32.f32 "
                        "{%0,%1,%2,%3}, {%4,%5,%6,%7}, {%8,%9}, {%0,%1,%2,%3};"
                        : "+f"(acc[i][j][0]), "+f"(acc[i][j][1]),
                          "+f"(acc[i][j][2]), "+f"(acc[i][j][3])
                        : "r"(a[i][0]), "r"(a[i][1]), "r"(a[i][2]), "r"(a[i][3]),
                          "r"(b[j][0]), "r"(b[j][1]));
                }
        }
        __syncthreads();
    }
    #pragma unroll
    for (int i=0;i<4;i++) {
        int row0 = bm + wm64 + i*16 + qr;
        #pragma unroll
        for (int j=0;j<4;j++) {
            int col0 = bn + wn32 + j*8 + qc*2;
            *(float2*)(C + (size_t)row0*N + col0)     = make_float2(acc[i][j][0], acc[i][j][1]);
            *(float2*)(C + (size_t)(row0+8)*N + col0) = make_float2(acc[i][j][2], acc[i][j][3]);
        }
    }
}

// ---------------- fp16 tensor-core flash self-attention -------------------------
#define KSH 24
#define VSH 1032
#define PSH 72
#define FLASH_SMEM ((1024*KSH + 16*VSH + 8*16*PSH)*2)

#define MMA_F16(acc, a, b0, b1) \
    asm volatile( \
        "mma.sync.aligned.m16n8k16.row.col.f32.f16.f16.f32 " \
        "{%0,%1,%2,%3}, {%4,%5,%6,%7}, {%8,%9}, {%0,%1,%2,%3};" \
        : "+f"((acc)[0]), "+f"((acc)[1]), "+f"((acc)[2]), "+f"((acc)[3]) \
        : "r"((a)[0]), "r"((a)[1]), "r"((a)[2]), "r"((a)[3]), \
          "r"(b0), "r"(b1))

__global__ __launch_bounds__(256) void flash_attn_kernel(
    const __half* __restrict__ qkv, __half* __restrict__ ao)
{
    extern __shared__ __half fsm[];
    __half* Ks = fsm;
    __half* Vs = fsm + 1024*KSH;
    __half* Ps = Vs + 16*VSH + (threadIdx.x >> 5)*16*PSH;

    const int b = blockIdx.x >> 6;
    const int h = blockIdx.x & 63;
    const int qt = blockIdx.y;
    const int tid = threadIdx.x;
    const int lane = tid & 31;
    const int warp = tid >> 5;
    const int qr = lane >> 2;
    const int qc = lane & 3;

    const __half* base = qkv + (size_t)b*T_SEQ*3*D + h*HD;

    for (int r = tid; r < T_SEQ; r += 256) {
        const uint32_t* kr = (const uint32_t*)(base + (size_t)r*3*D + D);
        #pragma unroll
        for (int i=0;i<8;i++) *(uint32_t*)(Ks + r*KSH + i*2) = kr[i];
        const __half* vr = base + (size_t)r*3*D + 2*D;
        #pragma unroll
        for (int d=0; d<16; d++) Vs[d*VSH + r] = vr[d];
    }

    const int q0 = qt*256 + warp*32;
    const half2 qs = __floats2half2_rn(0.25f, 0.25f);
    uint32_t aQ[2][4];
    #pragma unroll
    for (int mt=0; mt<2; mt++) {
        int r0 = q0 + mt*16 + qr;
        half2 v0 = __hmul2(*(const half2*)(base + (size_t)r0*3*D + 2*qc), qs);
        half2 v1 = __hmul2(*(const half2*)(base + (size_t)(r0+8)*3*D + 2*qc), qs);
        half2 v2 = __hmul2(*(const half2*)(base + (size_t)r0*3*D + 2*qc + 8), qs);
        half2 v3 = __hmul2(*(const half2*)(base + (size_t)(r0+8)*3*D + 2*qc + 8), qs);
        aQ[mt][0] = *(uint32_t*)&v0; aQ[mt][1] = *(uint32_t*)&v1;
        aQ[mt][2] = *(uint32_t*)&v2; aQ[mt][3] = *(uint32_t*)&v3;
    }
    __syncthreads();

    float mstate[2][2], lstate[2][2], oacc[2][2][4];
    #pragma unroll
    for (int mt=0; mt<2; mt++) {
        mstate[mt][0] = -1e30f; mstate[mt][1] = -1e30f;
        lstate[mt][0] = 0.f;    lstate[mt][1] = 0.f;
        #pragma unroll
        for (int nt=0; nt<2; nt++)
            #pragma unroll
            for (int e=0; e<4; e++) oacc[mt][nt][e] = 0.f;
    }

    for (int nc = 0; nc < 16; nc++) {
        const int kb = nc*64;
        #pragma unroll
        for (int mt=0; mt<2; mt++) {
            float sacc[8][4];
            #pragma unroll
            for (int nt=0; nt<8; nt++) {
                sacc[nt][0]=0.f; sacc[nt][1]=0.f; sacc[nt][2]=0.f; sacc[nt][3]=0.f;
                const int key = kb + nt*8 + qr;
                uint32_t b0 = *(const uint32_t*)(Ks + key*KSH + 2*qc);
                uint32_t b1 = *(const uint32_t*)(Ks + key*KSH + 2*qc + 8);
                MMA_F16(sacc[nt], aQ[mt], b0, b1);
            }
            float r0max = -1e30f, r1max = -1e30f;
            #pragma unroll
            for (int nt=0; nt<8; nt++) {
                r0max = fmaxf(r0max, fmaxf(sacc[nt][0], sacc[nt][1]));
                r1max = fmaxf(r1max, fmaxf(sacc[nt][2], sacc[nt][3]));
            }
            r0max = fmaxf(r0max, __shfl_xor_sync(0xFFFFFFFFu, r0max, 1));
            r0max = fmaxf(r0max, __shfl_xor_sync(0xFFFFFFFFu, r0max, 2));
            r1max = fmaxf(r1max, __shfl_xor_sync(0xFFFFFFFFu, r1max, 1));
            r1max = fmaxf(r1max, __shfl_xor_sync(0xFFFFFFFFu, r1max, 2));
            float mnew0 = fmaxf(mstate[mt][0], r0max);
            float mnew1 = fmaxf(mstate[mt][1], r1max);
            float corr0 = __expf(mstate[mt][0] - mnew0);
            float corr1 = __expf(mstate[mt][1] - mnew1);
            mstate[mt][0] = mnew0; mstate[mt][1] = mnew1;

            float rs0 = 0.f, rs1 = 0.f;
            #pragma unroll
            for (int nt=0; nt<8; nt++) {
                float p0 = __expf(sacc[nt][0] - mnew0);
                float p1 = __expf(sacc[nt][1] - mnew0);
                float p2 = __expf(sacc[nt][2] - mnew1);
                float p3 = __expf(sacc[nt][3] - mnew1);
                rs0 += p0 + p1; rs1 += p2 + p3;
                *(half2*)(Ps + qr*PSH + nt*8 + 2*qc)     = __floats2half2_rn(p0, p1);
                *(half2*)(Ps + (qr+8)*PSH + nt*8 + 2*qc) = __floats2half2_rn(p2, p3);
            }
            rs0 += __shfl_xor_sync(0xFFFFFFFFu, rs0, 1);
            rs0 += __shfl_xor_sync(0xFFFFFFFFu, rs0, 2);
            rs1 += __shfl_xor_sync(0xFFFFFFFFu, rs1, 1);
            rs1 += __shfl_xor_sync(0xFFFFFFFFu, rs1, 2);
            lstate[mt][0] = lstate[mt][0]*corr0 + rs0;
            lstate[mt][1] = lstate[mt][1]*corr1 + rs1;
            #pragma unroll
            for (int nt=0; nt<2; nt++) {
                oacc[mt][nt][0] *= corr0; oacc[mt][nt][1] *= corr0;
                oacc[mt][nt][2] *= corr1; oacc[mt][nt][3] *= corr1;
            }
            __syncwarp();
            #pragma unroll
            for (int ks=0; ks<4; ks++) {
                uint32_t a[4];
                a[0] = *(const uint32_t*)(Ps + qr*PSH + ks*16 + 2*qc);
                a[1] = *(const uint32_t*)(Ps + (qr+8)*PSH + ks*16 + 2*qc);
                a[2] = *(const uint32_t*)(Ps + qr*PSH + ks*16 + 2*qc + 8);
                a[3] = *(const uint32_t*)(Ps + (qr+8)*PSH + ks*16 + 2*qc + 8);
                #pragma unroll
                for (int nt=0; nt<2; nt++) {
                    const __half* vb = Vs + (nt*8+qr)*VSH + kb + ks*16;
                    uint32_t b0 = *(const uint32_t*)(vb + 2*qc);
                    uint32_t b1 = *(const uint32_t*)(vb + 2*qc + 8);
                    MMA_F16(oacc[mt][nt], a, b0, b1);
                }
            }
            __syncwarp();
        }
    }

    #pragma unroll
    for (int mt=0; mt<2; mt++) {
        float inv0 = 1.f/lstate[mt][0];
        float inv1 = 1.f/lstate[mt][1];
        int row0 = q0 + mt*16 + qr;
        #pragma unroll
        for (int nt=0; nt<2; nt++) {
            int col = h*HD + nt*8 + 2*qc;
            __half* o0 = ao + ((size_t)b*T_SEQ + row0)*D + col;
            __half* o1 = ao + ((size_t)b*T_SEQ + row0 + 8)*D + col;
            *(half2*)o0 = __floats2half2_rn(oacc[mt][nt][0]*inv0, oacc[mt][nt][1]*inv0);
            *(half2*)o1 = __floats2half2_rn(oacc[mt][nt][2]*inv1, oacc[mt][nt][3]*inv1);
        }
    }
}

// fold LN2 gamma into K' and compute per-slot constants:
// K''[row][d] = K'[row][d]*g2[d]; c1[row]=sum K''; c2[row]=sum beta2*K'
__global__ __launch_bounds__(128) void fold_kernel(
    const float* __restrict__ g2, const float* __restrict__ b2ln)
{
    __shared__ float s1[128], s2[128];
    int row = blockIdx.x;      // 0..63 (b*16+mm)
    float* kr = g_K + (size_t)row*D;
    float c1 = 0.f, c2 = 0.f;
    for (int d = threadIdx.x; d < D; d += 128) {
        float kv = kr[d];
        float kk = kv * g2[d];
        kr[d] = kk;
        c1 += kk;
        c2 += kv * b2ln[d];
    }
    s1[threadIdx.x] = c1; s2[threadIdx.x] = c2;
    __syncthreads();
    for (int off=64; off; off>>=1) {
        if (threadIdx.x < off) {
            s1[threadIdx.x]+=s1[threadIdx.x+off];
            s2[threadIdx.x]+=s2[threadIdx.x+off];
        }
        __syncthreads();
    }
    if (threadIdx.x == 0) {
        g_cc[row] = s1[0];
        g_cc[64 + row] = s2[0];
    }
}

// ---------------- cross-attention with fused LN2 --------------------------------
__global__ __launch_bounds__(256) void cross_attn_kernel(
    const float* __restrict__ Km, const float* __restrict__ Vm,
    float* __restrict__ xo)
{
    extern __shared__ float csm[];
    float* Ks = csm;
    float* Vs = csm + NMEM*D;
    int b = blockIdx.x >> 2;
    int chunk = blockIdx.x & 3;
    for (int i=threadIdx.x; i<NMEM*D; i+=256) {
        Ks[i] = Km[(size_t)b*NMEM*D + i];
        Vs[i] = Vm[(size_t)b*NMEM*D + i];
    }
    __syncthreads();
    int t = chunk*256 + threadIdx.x;
    float* xrow = xo + ((size_t)b*T_SEQ + t)*D;
    const float4* qrow = (const float4*)xrow;
    float s[16];
    #pragma unroll
    for (int mm=0;mm<16;mm++) s[mm]=0.f;
    float sum = 0.f, sq = 0.f;
    for (int k4=0;k4<D/4;k4++) {
        float4 qv = qrow[k4];
        sum += qv.x+qv.y+qv.z+qv.w;
        sq  += qv.x*qv.x + qv.y*qv.y + qv.z*qv.z + qv.w*qv.w;
        #pragma unroll
        for (int mm=0;mm<16;mm++) {
            const float* kr = Ks + mm*D + k4*4;
            s[mm] += qv.x*kr[0] + qv.y*kr[1] + qv.z*kr[2] + qv.w*kr[3];
        }
    }
    float mu = sum*(1.0f/D);
    float var = sq*(1.0f/D) - mu*mu;
    float rstd = rsqrtf(var + 1e-5f);
    float mx = -1e30f;
    #pragma unroll
    for (int mm=0;mm<16;mm++) {
        s[mm] = (rstd*s[mm] - rstd*mu*g_cc[b*16+mm] + g_cc[64 + b*16+mm]) * 0.03125f;
        mx = fmaxf(mx, s[mm]);
    }
    float ssum = 0.f;
    #pragma unroll
    for (int mm=0;mm<16;mm++) { s[mm] = __expf(s[mm]-mx); ssum += s[mm]; }
    float inv = 1.f/ssum;
    #pragma unroll
    for (int mm=0;mm<16;mm++) s[mm] *= inv;
    for (int c=0;c<D;c+=4) {
        float4 o = *(const float4*)(xrow + c);
        #pragma unroll
        for (int mm=0;mm<16;mm++) {
            const float* vr = Vs + mm*D + c;
            o.x += s[mm]*vr[0]; o.y += s[mm]*vr[1];
            o.z += s[mm]*vr[2]; o.w += s[mm]*vr[3];
        }
        *(float4*)(xrow + c) = o;
    }
}

// ---------------- memory path -------------------------------------------------
__global__ __launch_bounds__(256) void mean_kernel(const float* __restrict__ x,
                                                   float* __restrict__ mh) {
    __shared__ float sred[256];
    int b = blockIdx.x, cb = blockIdx.y*128;
    int c = threadIdx.x & 127, half = threadIdx.x >> 7;
    const float* p = x + (size_t)b*T_SEQ*D + (size_t)half*512*D + cb + c;
    float s = 0.f;
    #pragma unroll 4
    for (int t=0;t<512;t++) s += p[(size_t)t*D];
    sred[threadIdx.x] = s;
    __syncthreads();
    if (half == 0)
        mh[b*D + cb + c] = (sred[threadIdx.x] + sred[threadIdx.x+128]) * (1.f/T_SEQ);
}

__global__ __launch_bounds__(256) void base_gemv(
    const float* __restrict__ Wz, const float* __restrict__ Wr, const float* __restrict__ Wc,
    const float* __restrict__ bz, const float* __restrict__ br, const float* __restrict__ bc)
{
    int gid = blockIdx.x*8 + (threadIdx.x >> 5);
    int lane = threadIdx.x & 31;
    int g = gid >> 12;
    int rem = gid & 4095;
    int b = rem >> 10;
    int col = rem & 1023;
    const float* W    = (g==0) ? Wz : ((g==1) ? Wr : Wc);
    const float* bias = (g==0) ? bz : ((g==1) ? br : bc);
    const float* wrow = W + (size_t)col*2048;
    const float* mrow = g_meanh + b*D;
    float acc = 0.f;
    #pragma unroll
    for (int k0=0;k0<1024;k0+=128) {
        float4 w = *(const float4*)(wrow + k0 + lane*4);
        float4 m = *(const float4*)(mrow + k0 + lane*4);
        acc += w.x*m.x + w.y*m.y + w.z*m.z + w.w*m.w;
    }
    #pragma unroll
    for (int o=16;o;o>>=1) acc += __shfl_xor_sync(0xFFFFFFFFu, acc, o);
    if (lane == 0) g_base[gid] = acc + bias[col];
}

__device__ __forceinline__ void tile64x64(
    const float* __restrict__ A, const float* __restrict__ B, int ldb,
    float (&acc)[4][4])
{
    __shared__ float As[32][65];
    __shared__ float Bs[32][65];
    const int tid = threadIdx.x;
    const int r  = tid >> 2;
    const int kq = (tid & 3) << 3;
    const int tx = tid & 15;
    const int ty = tid >> 4;
    for (int k0 = 0; k0 < 1024; k0 += 32) {
        float4 a0 = *(const float4*)(A + (size_t)r*1024 + k0 + kq);
        float4 a1 = *(const float4*)(A + (size_t)r*1024 + k0 + kq + 4);
        float4 b0 = *(const float4*)(B + (size_t)r*ldb  + k0 + kq);
        float4 b1 = *(const float4*)(B + (size_t)r*ldb  + k0 + kq + 4);
        __syncthreads();
        As[kq+0][r]=a0.x; As[kq+1][r]=a0.y; As[kq+2][r]=a0.z; As[kq+3][r]=a0.w;
        As[kq+4][r]=a1.x; As[kq+5][r]=a1.y; As[kq+6][r]=a1.z; As[kq+7][r]=a1.w;
        Bs[kq+0][r]=b0.x; Bs[kq+1][r]=b0.y; Bs[kq+2][r]=b0.z; Bs[kq+3][r]=b0.w;
        Bs[kq+4][r]=b1.x; Bs[kq+5][r]=b1.y; Bs[kq+6][r]=b1.z; Bs[kq+7][r]=b1.w;
        __syncthreads();
        #pragma unroll
        for (int kk=0;kk<32;kk++) {
            float a[4], b[4];
            #pragma unroll
            for (int i=0;i<4;i++) a[i] = As[kk][ty*4+i];
            #pragma unroll
            for (int j=0;j<4;j++) b[j] = Bs[kk][tx*4+j];
            #pragma unroll
            for (int i=0;i<4;i++)
                #pragma unroll
                for (int j=0;j<4;j++) acc[i][j] += a[i]*b[j];
        }
    }
}

__global__ __launch_bounds__(256) void zr_pre(
    const float* __restrict__ mem, const float* __restrict__ Wz,
    const float* __restrict__ Wr)
{
    int g = blockIdx.y;
    int ct = blockIdx.x;
    const float* W = (g ? Wr : Wz) + (size_t)(ct*64)*2048 + 1024;
    float acc[4][4];
    #pragma unroll
    for (int i=0;i<4;i++)
        #pragma unroll
        for (int j=0;j<4;j++) acc[i][j]=0.f;
    tile64x64(mem, W, 2048, acc);
    float* out = g ? g_rpre : g_zpre;
    const int tx = threadIdx.x & 15, ty = threadIdx.x >> 4;
    #pragma unroll
    for (int i=0;i<4;i++) {
        int row = ty*4+i;
        #pragma unroll
        for (int j=0;j<4;j++) out[row*1024 + ct*64 + tx*4+j] = acc[i][j];
    }
}

__global__ void combine_kernel(const float* __restrict__ mem) {
    int idx = blockIdx.x*blockDim.x + threadIdx.x;
    int row = idx >> 10, col = idx & 1023, b = row >> 4;
    float z = 1.f/(1.f + __expf(-(g_zpre[idx] + g_base[0*4096 + b*1024 + col])));
    float r = 1.f/(1.f + __expf(-(g_rpre[idx] + g_base[1*4096 + b*1024 + col])));
    g_z[idx] = z;
    g_rm[idx] = r * mem[idx];
}

__global__ __launch_bounds__(256) void c_gemm(
    const float* __restrict__ mem, const float* __restrict__ Wc,
    float* __restrict__ newmem)
{
    int ct = blockIdx.x;
    const float* W = Wc + (size_t)(ct*64)*2048 + 1024;
    float acc[4][4];
    #pragma unroll
    for (int i=0;i<4;i++)
        #pragma unroll
        for (int j=0;j<4;j++) acc[i][j]=0.f;
    tile64x64(g_rm, W, 2048, acc);
    const int tx = threadIdx.x & 15, ty = threadIdx.x >> 4;
    #pragma unroll
    for (int i=0;i<4;i++) {
        int row = ty*4+i;
        #pragma unroll
        for (int j=0;j<4;j++) {
            int col = ct*64 + tx*4+j;
            float v = acc[i][j] + g_base[2*4096 + (row>>4)*1024 + col];
            float c = tanhf(v);
            float z = g_z[row*1024+col];
            newmem[(size_t)row*1024+col] = (1.f - z)*mem[(size_t)row*1024+col] + z*c;
        }
    }
}

__global__ __launch_bounds__(256) void kv2_gemm(const float* __restrict__ newmem)
{
    int which = blockIdx.y;
    int ct = blockIdx.x;
    const float* W = (which ? g_wv : g_wk) + (size_t)(ct*64)*1024;
    float acc[4][4];
    #pragma unroll
    for (int i=0;i<4;i++)
        #pragma unroll
        for (int j=0;j<4;j++) acc[i][j]=0.f;
    tile64x64(newmem, W, 1024, acc);
    float* out = which ? g_V : g_K;
    const int tx = threadIdx.x & 15, ty = threadIdx.x >> 4;
    #pragma unroll
    for (int i=0;i<4;i++) {
        int row = ty*4+i;
        #pragma unroll
        for (int j=0;j<4;j++) {
            int col = ct*64 + tx*4+j;
            out[(size_t)row*1024+col] = acc[i][j];
        }
    }
}

// ---------------- host launcher -------------------------------------------------
extern "C" void kernel_launch(void* const* d_in, const int* in_sizes, int n_in,
                              void* d_out, int out_size)
{
    const float* x          = (const float*)d_in[0];
    const float* memory     = (const float*)d_in[1];
    const float* ln1_g      = (const float*)d_in[2];
    const float* ln1_b      = (const float*)d_in[3];
    const float* ln2_g      = (const float*)d_in[4];
    const float* ln2_b      = (const float*)d_in[5];
    const float* ln3_g      = (const float*)d_in[6];
    const float* ln3_b      = (const float*)d_in[7];
    const float* in_proj_w  = (const float*)d_in[8];
    const float* in_proj_b  = (const float*)d_in[9];
    const float* attn_out_w = (const float*)d_in[10];
    const float* attn_out_b = (const float*)d_in[11];
    const float* Wz_w       = (const float*)d_in[12];
    const float* Wz_b       = (const float*)d_in[13];
    const float* Wr_w       = (const float*)d_in[14];
    const float* Wr_b       = (const float*)d_in[15];
    const float* Wc_w       = (const float*)d_in[16];
    const float* Wc_b       = (const float*)d_in[17];
    const float* mq_w       = (const float*)d_in[18];
    const float* mk_w       = (const float*)d_in[19];
    const float* mv_w       = (const float*)d_in[20];
    const float* mo_w       = (const float*)d_in[21];
    const float* W1         = (const float*)d_in[22];
    const float* b1         = (const float*)d_in[23];
    const float* W2         = (const float*)d_in[24];
    const float* b2         = (const float*)d_in[25];

    float* xo = (float*)d_out;
    float* newmem = xo + (size_t)ROWS*D;

    float *p_K, *p_V, *p_w, *p_mh, *p_wk, *p_wv;
    __half *p_hh, *p_hqkv, *p_hao, *p_hffn, *p_hw;
    cudaGetSymbolAddress((void**)&p_K,    g_K);
    cudaGetSymbolAddress((void**)&p_V,    g_V);
    cudaGetSymbolAddress((void**)&p_w,    g_w);
    cudaGetSymbolAddress((void**)&p_mh,   g_meanh);
    cudaGetSymbolAddress((void**)&p_wk,   g_wk);
    cudaGetSymbolAddress((void**)&p_wv,   g_wv);
    cudaGetSymbolAddress((void**)&p_hh,   h_h);
    cudaGetSymbolAddress((void**)&p_hqkv, h_qkv);
    cudaGetSymbolAddress((void**)&p_hao,  h_ao);
    cudaGetSymbolAddress((void**)&p_hffn, h_ffn);
    cudaGetSymbolAddress((void**)&p_hw,   h_w);

    static cudaStream_t s2 = nullptr;
    static cudaEvent_t evStart = nullptr, evCvt = nullptr, evFork = nullptr, evMem = nullptr;
    static bool tried = false, ok = false;
    if (!tried) {
        tried = true;
        ok = (cudaStreamCreateWithFlags(&s2, cudaStreamNonBlocking) == cudaSuccess) &&
             (cudaEventCreateWithFlags(&evStart, cudaEventDisableTiming) == cudaSuccess) &&
             (cudaEventCreateWithFlags(&evCvt,   cudaEventDisableTiming) == cudaSuccess) &&
             (cudaEventCreateWithFlags(&evFork,  cudaEventDisableTiming) == cudaSuccess) &&
             (cudaEventCreateWithFlags(&evMem,   cudaEventDisableTiming) == cudaSuccess);
    }
    cudaStream_t sb = ok ? s2 : (cudaStream_t)0;

    cudaFuncSetAttribute(flash_attn_kernel, cudaFuncAttributeMaxDynamicSharedMemorySize, FLASH_SMEM);
    cudaFuncSetAttribute(cross_attn_kernel, cudaFuncAttributeMaxDynamicSharedMemorySize, 131072);
    const int GSM = SMEM_FLOATS * 4;
    cudaFuncSetAttribute(gemm_tf32<0,0,0,0>, cudaFuncAttributeMaxDynamicSharedMemorySize, GSM);
    cudaFuncSetAttribute(gemm_fp16<0,1,0,1>, cudaFuncAttributeMaxDynamicSharedMemorySize, HSMEM_BYTES);
    cudaFuncSetAttribute(gemm_fp16<0,1,1,0>, cudaFuncAttributeMaxDynamicSharedMemorySize, HSMEM_BYTES);
    cudaFuncSetAttribute(gemm_fp16<1,1,0,1>, cudaFuncAttributeMaxDynamicSharedMemorySize, HSMEM_BYTES);

    // ---- early hidden phase on sb ----
    if (ok) { cudaEventRecord(evStart, 0); cudaStreamWaitEvent(sb, evStart, 0); }
    cvt_fp16_kernel<<<3072, 256, 0, sb>>>(in_proj_w,  p_hw + HOFF_INP,  3*1024*1024/4);
    cvt_fp16_kernel<<<1024, 256, 0, sb>>>(attn_out_w, p_hw + HOFF_AOUT, 1024*1024/4);
    cvt_fp16_kernel<<<4096, 256, 0, sb>>>(W1,         p_hw + HOFF_W1,   4*1024*1024/4);
    cvt_fp16_kernel<<<4096, 256, 0, sb>>>(W2,         p_hw + HOFF_W2,   4*1024*1024/4);
    if (ok) cudaEventRecord(evCvt, sb);
    cvt_tf32_kernel<<<1024, 256, 0, sb>>>(mo_w, p_w + OFF_MO, 1024*1024/4);
    transpose_tf32<<<dim3(32,32), dim3(32,8), 0, sb>>>(mq_w, p_w + OFF_MQT);
    transpose_tf32<<<dim3(32,32), dim3(32,8), 0, sb>>>(mk_w, p_w + OFF_MKT);
    transpose_tf32<<<dim3(32,32), dim3(32,8), 0, sb>>>(mv_w, p_w + OFF_MVT);
    gemm_tf32<0,0,0,0><<<dim3(8,8), 256, GSM, sb>>>(p_w + OFF_MQT, p_w + OFF_MKT, nullptr, nullptr, p_wk, 1024, 1024, 1024);
    gemm_tf32<0,0,0,0><<<dim3(8,8), 256, GSM, sb>>>(p_w + OFF_MO,  p_w + OFF_MVT, nullptr, nullptr, p_wv, 1024, 1024, 1024);
    zr_pre<<<dim3(16,2), 256, 0, sb>>>(memory, Wz_w, Wr_w);

    // ---- main path ----
    ln_kernel_h<<<ROWS, 256>>>(x, ln1_g, ln1_b, p_hh);
    if (ok) cudaStreamWaitEvent(0, evCvt, 0);

    gemm_fp16<0,1,0,1><<<dim3(3*D/128, ROWS/128), 256, HSMEM_BYTES>>>(p_hh, p_hw + HOFF_INP, in_proj_b, nullptr, p_hqkv, ROWS, 3*D, D);
    flash_attn_kernel<<<dim3(BATCH*NHEADS, 4), 256, FLASH_SMEM>>>(p_hqkv, p_hao);
    gemm_fp16<0,1,1,0><<<dim3(D/128, ROWS/128), 256, HSMEM_BYTES>>>(p_hao, p_hw + HOFF_AOUT, attn_out_b, x, xo, ROWS, D, D);

    // ---- fork memory path onto sb ----
    if (ok) { cudaEventRecord(evFork, 0); cudaStreamWaitEvent(sb, evFork, 0); }
    mean_kernel<<<dim3(BATCH, 8), 256, 0, sb>>>(xo, p_mh);
    base_gemv<<<1536, 256, 0, sb>>>(Wz_w, Wr_w, Wc_w, Wz_b, Wr_b, Wc_b);
    combine_kernel<<<BATCH*NMEM*D/256, 256, 0, sb>>>(memory);
    c_gemm<<<16, 256, 0, sb>>>(memory, Wc_w, newmem);
    kv2_gemm<<<dim3(16, 2), 256, 0, sb>>>(newmem);
    fold_kernel<<<BATCH*NMEM, 128, 0, sb>>>(ln2_g, ln2_b);
    if (ok) cudaEventRecord(evMem, sb);

    // ---- main path: fused LN2 + cross-attention (in-place residual) ----
    if (ok) cudaStreamWaitEvent(0, evMem, 0);
    cross_attn_kernel<<<BATCH*4, 256, 131072>>>(p_K, p_V, xo);

    // FFN
    ln_kernel_h<<<ROWS, 256>>>(xo, ln3_g, ln3_b, p_hh);
    gemm_fp16<1,1,0,1><<<dim3(4*D/128, ROWS/128), 256, HSMEM_BYTES>>>(p_hh, p_hw + HOFF_W1, b1, nullptr, p_hffn, ROWS, 4*D, D);
    gemm_fp16<0,1,1,0><<<dim3(D/128, ROWS/128), 256, HSMEM_BYTES>>>(p_hffn, p_hw + HOFF_W2, b2, xo, xo, ROWS, D, 4*D);
}

// round 16
// speedup vs baseline: 1.0382x; 1.0209x over previous
#include <cuda_runtime.h>
#include <cuda_fp16.h>
#include <math.h>
#include <stdint.h>

#define D 1024
#define T_SEQ 1024
#define BATCH 4
#define NMEM 16
#define NHEADS 64
#define HD 16
#define ROWS (BATCH*T_SEQ)   // 4096

// ---------------- scratch (device globals; no runtime allocation) ----------------
__device__ float g_h[ROWS*D];            // LN2 output (float, feeds cross-attn)
__device__ __half h_h[ROWS*D];           // LN1/LN3 outputs (fp16)
__device__ __half h_qkv[ROWS*3*D];       // QKV (fp16)
__device__ __half h_ao[ROWS*D];          // self-attention output (fp16)
__device__ __half h_ffn[ROWS*4*D];       // FFN hidden (fp16)
__device__ float g_meanh[BATCH*D];
__device__ float g_base[3*BATCH*D];
__device__ float g_zpre[BATCH*NMEM*D];
__device__ float g_rpre[BATCH*NMEM*D];
__device__ float g_z[BATCH*NMEM*D];
__device__ float g_rm[BATCH*NMEM*D];
__device__ float g_K[BATCH*NMEM*D];
__device__ float g_V[BATCH*NMEM*D];
__device__ float g_wk[1024*1024];        // Wk' = mq^T @ mk
__device__ float g_wv[1024*1024];        // Wv' = mo @ mv
__device__ float g_w[8*1024*1024];       // float scratch for fold path
__device__ __half h_w[12*1024*1024];     // fp16 weight copies

#define OFF_MQT   0
#define OFF_MO    (1*1024*1024)
#define OFF_MKT   (2*1024*1024)
#define OFF_MVT   (3*1024*1024)
#define HOFF_INP  0
#define HOFF_AOUT (3*1024*1024)
#define HOFF_W1   (4*1024*1024)
#define HOFF_W2   (8*1024*1024)

__device__ __forceinline__ float to_tf32(float v) {
    uint32_t r;
    asm("cvt.rna.tf32.f32 %0, %1;" : "=r"(r) : "f"(v));
    return __uint_as_float(r);
}

// ---------------- utility kernels ----------------
__global__ void cvt_tf32_kernel(const float* __restrict__ src, float* __restrict__ dst, int n4) {
    int i = blockIdx.x*blockDim.x + threadIdx.x;
    if (i < n4) {
        float4 v = ((const float4*)src)[i];
        v.x = to_tf32(v.x); v.y = to_tf32(v.y); v.z = to_tf32(v.z); v.w = to_tf32(v.w);
        ((float4*)dst)[i] = v;
    }
}

__global__ void cvt_fp16_kernel(const float* __restrict__ src, __half* __restrict__ dst, int n4) {
    int i = blockIdx.x*blockDim.x + threadIdx.x;
    if (i < n4) {
        float4 v = ((const float4*)src)[i];
        half2 lo = __floats2half2_rn(v.x, v.y);
        half2 hi = __floats2half2_rn(v.z, v.w);
        ((half2*)dst)[2*i]   = lo;
        ((half2*)dst)[2*i+1] = hi;
    }
}

__global__ __launch_bounds__(256) void transpose_tf32(
    const float* __restrict__ src, float* __restrict__ dst)
{
    __shared__ float tile[32][33];
    int x = blockIdx.x*32 + threadIdx.x;
    int y0 = blockIdx.y*32 + threadIdx.y;
    #pragma unroll
    for (int i=0;i<32;i+=8)
        tile[threadIdx.y+i][threadIdx.x] = src[(size_t)(y0+i)*1024 + x];
    __syncthreads();
    int x2 = blockIdx.y*32 + threadIdx.x;
    int y2 = blockIdx.x*32 + threadIdx.y;
    #pragma unroll
    for (int i=0;i<32;i+=8)
        dst[(size_t)(y2+i)*1024 + x2] = to_tf32(tile[threadIdx.x][threadIdx.y+i]);
}

// LayerNorm -> float output (LN2, feeds scalar cross-attn)
__global__ __launch_bounds__(256) void ln_kernel(
    const float* __restrict__ x, const float* __restrict__ g,
    const float* __restrict__ b, float* __restrict__ y)
{
    __shared__ float s1[256], s2[256];
    int row = blockIdx.x;
    const float4* xr = (const float4*)(x + (size_t)row*D);
    float4 v = xr[threadIdx.x];
    float sum = v.x+v.y+v.z+v.w;
    float sq  = v.x*v.x + v.y*v.y + v.z*v.z + v.w*v.w;
    s1[threadIdx.x]=sum; s2[threadIdx.x]=sq;
    __syncthreads();
    for (int off=128; off; off>>=1) {
        if (threadIdx.x < off) {
            s1[threadIdx.x]+=s1[threadIdx.x+off];
            s2[threadIdx.x]+=s2[threadIdx.x+off];
        }
        __syncthreads();
    }
    float mean = s1[0]*(1.0f/D);
    float var  = s2[0]*(1.0f/D) - mean*mean;
    float rstd = rsqrtf(var + 1e-5f);
    int c = threadIdx.x*4;
    float4 gg = *(const float4*)(g+c);
    float4 bb = *(const float4*)(b+c);
    float4 o;
    o.x = (v.x-mean)*rstd*gg.x + bb.x;
    o.y = (v.y-mean)*rstd*gg.y + bb.y;
    o.z = (v.z-mean)*rstd*gg.z + bb.z;
    o.w = (v.w-mean)*rstd*gg.w + bb.w;
    ((float4*)(y + (size_t)row*D))[threadIdx.x] = o;
}

// LayerNorm -> fp16 output (LN1/LN3, feeds fp16 GEMMs)
__global__ __launch_bounds__(256) void ln_kernel_h(
    const float* __restrict__ x, const float* __restrict__ g,
    const float* __restrict__ b, __half* __restrict__ y)
{
    __shared__ float s1[256], s2[256];
    int row = blockIdx.x;
    const float4* xr = (const float4*)(x + (size_t)row*D);
    float4 v = xr[threadIdx.x];
    float sum = v.x+v.y+v.z+v.w;
    float sq  = v.x*v.x + v.y*v.y + v.z*v.z + v.w*v.w;
    s1[threadIdx.x]=sum; s2[threadIdx.x]=sq;
    __syncthreads();
    for (int off=128; off; off>>=1) {
        if (threadIdx.x < off) {
            s1[threadIdx.x]+=s1[threadIdx.x+off];
            s2[threadIdx.x]+=s2[threadIdx.x+off];
        }
        __syncthreads();
    }
    float mean = s1[0]*(1.0f/D);
    float var  = s2[0]*(1.0f/D) - mean*mean;
    float rstd = rsqrtf(var + 1e-5f);
    int c = threadIdx.x*4;
    float4 gg = *(const float4*)(g+c);
    float4 bb = *(const float4*)(b+c);
    half2 lo = __floats2half2_rn((v.x-mean)*rstd*gg.x + bb.x, (v.y-mean)*rstd*gg.y + bb.y);
    half2 hi = __floats2half2_rn((v.z-mean)*rstd*gg.z + bb.z, (v.w-mean)*rstd*gg.w + bb.w);
    half2* yr = (half2*)(y + (size_t)row*D);
    yr[threadIdx.x*2]   = lo;
    yr[threadIdx.x*2+1] = hi;
}

__device__ __forceinline__ void cp16(uint32_t dst, const void* src) {
    asm volatile("cp.async.cg.shared.global [%0], [%1], 16;" :: "r"(dst), "l"(src));
}

#define LDM_X4(r0, r1, r2, r3, addr) \
    asm volatile("ldmatrix.sync.aligned.m8n8.x4.shared.b16 {%0,%1,%2,%3}, [%4];" \
        : "=r"(r0), "=r"(r1), "=r"(r2), "=r"(r3) : "r"(addr))

// ---------------- fp16 tensor-core GEMM: C(M,N) = A(M,K) @ B(N,K)^T -------------
// m16n8k16 HMMA, fp32 accum. 128x128 block, 8 warps (256 thr), 64x32 warp tile,
// BK=32, 4-stage cp.async ring, ldmatrix fragments, SINGLE sync per chunk.
// (bottom sync removed: iter-t prefetch overwrites buf (t-1)%4, and the top
//  sync of iter t already happens-after every warp's compute of iter t-1.)
#define HA_OFF(buf) ((buf)*10240)
#define HB_OFF(buf) (5120 + (buf)*10240)
#define HSMEM_BYTES (4*10240*2)   // 81920 B

template<int ACT, int BIASF, int RESF, int OUTHALF>
__global__ __launch_bounds__(256, 2) void gemm_fp16(
    const __half* __restrict__ A, const __half* __restrict__ B,
    const float* __restrict__ bias, const float* __restrict__ res,
    void* __restrict__ Cv, int M, int N, int K)
{
    extern __shared__ __half hsm[];
    float* Cf = (float*)Cv;
    __half* Ch = (__half*)Cv;
    const int tid = threadIdx.x;
    const int bm = blockIdx.y * 128;
    const int bn = blockIdx.x * 128;
    const int lane = tid & 31;
    const int warp = tid >> 5;
    const int wm64 = (warp & 1) * 64;
    const int wn32 = (warp >> 1) * 32;
    const int qr = lane >> 2;
    const int qc = lane & 3;
    uint32_t smem_u32 = (uint32_t)__cvta_generic_to_shared(hsm);

    const int a_row = wm64 + (lane & 7) + ((lane >> 3) & 1) * 8;  // + i*16
    const int a_kk  = (lane >> 4) * 8;
    const int b_row = wn32 + (lane & 7) + ((lane >= 16) ? 8 : 0); // + jp*16
    const int b_kk  = ((lane >> 3) & 1) * 8;

    const int ld_row = tid >> 2;        // 0..63 (+64 per rep)
    const int ld_seg = (tid & 3) * 8;   // halves

    float acc[4][4][4];
    #pragma unroll
    for (int i=0;i<4;i++)
        #pragma unroll
        for (int j=0;j<4;j++)
            #pragma unroll
            for (int e=0;e<4;e++) acc[i][j][e] = 0.f;

    const int NT = K >> 5;

    // prologue: prefetch stages 0..2
    #pragma unroll
    for (int p=0; p<3; p++) {
        const __half* Ab = A + (size_t)bm*K + p*32;
        const __half* Bb = B + (size_t)bn*K + p*32;
        #pragma unroll
        for (int rep=0; rep<2; rep++) {
            int row = rep*64 + ld_row;
            cp16(smem_u32 + (HA_OFF(p) + row*40 + ld_seg)*2, Ab + (size_t)row*K + ld_seg);
            cp16(smem_u32 + (HB_OFF(p) + row*40 + ld_seg)*2, Bb + (size_t)row*K + ld_seg);
        }
        asm volatile("cp.async.commit_group;");
    }

    for (int t = 0; t < NT; t++) {
        if (t + 3 <= NT)      asm volatile("cp.async.wait_group 2;");
        else if (t + 2 == NT) asm volatile("cp.async.wait_group 1;");
        else                  asm volatile("cp.async.wait_group 0;");
        __syncthreads();

        if (t + 3 < NT) {
            int buf = (t+3) & 3;
            int kb = (t+3) << 5;
            const __half* Ab = A + (size_t)bm*K + kb;
            const __half* Bb = B + (size_t)bn*K + kb;
            #pragma unroll
            for (int rep=0; rep<2; rep++) {
                int row = rep*64 + ld_row;
                cp16(smem_u32 + (HA_OFF(buf) + row*40 + ld_seg)*2, Ab + (size_t)row*K + ld_seg);
                cp16(smem_u32 + (HB_OFF(buf) + row*40 + ld_seg)*2, Bb + (size_t)row*K + ld_seg);
            }
            asm volatile("cp.async.commit_group;");
        }

        const uint32_t abuf = HA_OFF(t & 3);
        const uint32_t bbuf = HB_OFF(t & 3);

        #pragma unroll
        for (int ks = 0; ks < 2; ks++) {
            const int k0 = ks * 16;
            uint32_t a[4][4], b[4][2];
            #pragma unroll
            for (int i=0;i<4;i++) {
                uint32_t ad = smem_u32 + (abuf + (a_row + i*16)*40 + k0 + a_kk)*2;
                LDM_X4(a[i][0], a[i][1], a[i][2], a[i][3], ad);
            }
            #pragma unroll
            for (int jp=0; jp<2; jp++) {
                uint32_t bd = smem_u32 + (bbuf + (b_row + jp*16)*40 + k0 + b_kk)*2;
                LDM_X4(b[2*jp][0], b[2*jp][1], b[2*jp+1][0], b[2*jp+1][1], bd);
            }
            #pragma unroll
            for (int i=0;i<4;i++)
                #pragma unroll
                for (int j=0;j<4;j++) {
                    asm volatile(
                        "mma.sync.aligned.m16n8k16.row.col.f32.f16.f16.f32 "
                        "{%0,%1,%2,%3}, {%4,%5,%6,%7}, {%8,%9}, {%0,%1,%2,%3};"
                        : "+f"(acc[i][j][0]), "+f"(acc[i][j][1]),
                          "+f"(acc[i][j][2]), "+f"(acc[i][j][3])
                        : "r"(a[i][0]), "r"(a[i][1]), "r"(a[i][2]), "r"(a[i][3]),
                          "r"(b[j][0]), "r"(b[j][1]));
                }
        }
        // no bottom sync: top sync of next iteration orders compute-before-overwrite
    }

    #pragma unroll
    for (int i=0;i<4;i++) {
        int row0 = bm + wm64 + i*16 + qr;
        #pragma unroll
        for (int j=0;j<4;j++) {
            int col0 = bn + wn32 + j*8 + qc*2;
            float v0 = acc[i][j][0], v1 = acc[i][j][1];
            float v2 = acc[i][j][2], v3 = acc[i][j][3];
            if (BIASF) {
                float b0 = bias[col0], b1 = bias[col0+1];
                v0 += b0; v1 += b1; v2 += b0; v3 += b1;
            }
            if (ACT == 1) {
                v0 = 0.5f*v0*(1.f + erff(v0*0.70710678118654752f));
                v1 = 0.5f*v1*(1.f + erff(v1*0.70710678118654752f));
                v2 = 0.5f*v2*(1.f + erff(v2*0.70710678118654752f));
                v3 = 0.5f*v3*(1.f + erff(v3*0.70710678118654752f));
            }
            if (RESF) {
                v0 += res[(size_t)row0*N + col0];
                v1 += res[(size_t)row0*N + col0 + 1];
                v2 += res[(size_t)(row0+8)*N + col0];
                v3 += res[(size_t)(row0+8)*N + col0 + 1];
            }
            if (OUTHALF) {
                *(half2*)(Ch + (size_t)row0*N + col0)     = __floats2half2_rn(v0, v1);
                *(half2*)(Ch + (size_t)(row0+8)*N + col0) = __floats2half2_rn(v2, v3);
            } else {
                *(float2*)(Cf + (size_t)row0*N + col0)     = make_float2(v0, v1);
                *(float2*)(Cf + (size_t)(row0+8)*N + col0) = make_float2(v2, v3);
            }
        }
    }
}

// ---------------- legacy mma.sync tf32 GEMM (hidden weight-fold GEMMs) ----------
#define SMEM_FLOATS (4*4608)
#define A_OFFS(buf) ((buf)*4608)
#define B_OFFS(buf) (9216 + (buf)*4608)

template<int ACT, int BIASF, int RESF, int TF32OUT>
__global__ __launch_bounds__(256, 2) void gemm_tf32(
    const float* __restrict__ A, const float* __restrict__ B,
    const float* __restrict__ bias, const float* __restrict__ res,
    float* __restrict__ C, int M, int N, int K)
{
    extern __shared__ float sm[];
    const int tid = threadIdx.x;
    const int bm = blockIdx.y * 128;
    const int bn = blockIdx.x * 128;
    const int lane = tid & 31;
    const int warp = tid >> 5;
    const int wm64 = (warp & 1) * 64;
    const int wn32 = (warp >> 1) * 32;
    const int qr = lane >> 2;
    const int qc = lane & 3;
    uint32_t smem_u32 = (uint32_t)__cvta_generic_to_shared(sm);
    const int lrow = tid >> 3;
    const int lkq  = (tid & 7) * 4;

    float acc[4][4][4];
    #pragma unroll
    for (int i=0;i<4;i++)
        #pragma unroll
        for (int j=0;j<4;j++)
            #pragma unroll
            for (int e=0;e<4;e++) acc[i][j][e] = 0.f;

    const int NT = K >> 5;
    {
        const float* Ab = A + (size_t)bm*K;
        const float* Bb = B + (size_t)bn*K;
        #pragma unroll
        for (int rep=0; rep<4; rep++) {
            int row = rep*32 + lrow;
            cp16(smem_u32 + (A_OFFS(0) + row*36 + lkq)*4, Ab + (size_t)row*K + lkq);
            cp16(smem_u32 + (B_OFFS(0) + row*36 + lkq)*4, Bb + (size_t)row*K + lkq);
        }
        asm volatile("cp.async.commit_group;");
    }
    for (int t = 0; t < NT; t++) {
        if (t + 1 < NT) {
            int buf = (t+1) & 1;
            int kb = (t+1) << 5;
            const float* Ab = A + (size_t)bm*K + kb;
            const float* Bb = B + (size_t)bn*K + kb;
            #pragma unroll
            for (int rep=0; rep<4; rep++) {
                int row = rep*32 + lrow;
                cp16(smem_u32 + (A_OFFS(buf) + row*36 + lkq)*4, Ab + (size_t)row*K + lkq);
                cp16(smem_u32 + (B_OFFS(buf) + row*36 + lkq)*4, Bb + (size_t)row*K + lkq);
            }
            asm volatile("cp.async.commit_group;");
            asm volatile("cp.async.wait_group 1;");
        } else {
            asm volatile("cp.async.wait_group 0;");
        }
        __syncthreads();
        const float* sA = sm + A_OFFS(t & 1);
        const float* sB = sm + B_OFFS(t & 1);
        #pragma unroll
        for (int ks = 0; ks < 4; ks++) {
            const int k0 = ks * 8;
            uint32_t a[4][4], b[4][2];
            #pragma unroll
            for (int i=0;i<4;i++) {
                int r = wm64 + i*16 + qr;
                a[i][0] = __float_as_uint(sA[r*36 + k0 + qc]);
                a[i][1] = __float_as_uint(sA[(r+8)*36 + k0 + qc]);
                a[i][2] = __float_as_uint(sA[r*36 + k0 + qc + 4]);
                a[i][3] = __float_as_uint(sA[(r+8)*36 + k0 + qc + 4]);
            }
            #pragma unroll
            for (int j=0;j<4;j++) {
                int n = wn32 + j*8 + qr;
                b[j][0] = __float_as_uint(sB[n*36 + k0 + qc]);
                b[j][1] = __float_as_uint(sB[n*36 + k0 + qc + 4]);
            }
            #pragma unroll
            for (int i=0;i<4;i++)
                #pragma unroll
                for (int j=0;j<4;j++) {
                    asm volatile(
                        "mma.sync.aligned.m16n8k8.row.col.f32.tf32.tf32.f32 "
                        "{%0,%1,%2,%3}, {%4,%5,%6,%7}, {%8,%9}, {%0,%1,%2,%3};"
                        : "+f"(acc[i][j][0]), "+f"(acc[i][j][1]),
                          "+f"(acc[i][j][2]), "+f"(acc[i][j][3])
                        : "r"(a[i][0]), "r"(a[i][1]), "r"(a[i][2]), "r"(a[i][3]),
                          "r"(b[j][0]), "r"(b[j][1]));
                }
        }
        __syncthreads();
    }
    #pragma unroll
    for (int i=0;i<4;i++) {
        int row0 = bm + wm64 + i*16 + qr;
        #pragma unroll
        for (int j=0;j<4;j++) {
            int col0 = bn + wn32 + j*8 + qc*2;
            *(float2*)(C + (size_t)row0*N + col0)     = make_float2(acc[i][j][0], acc[i][j][1]);
            *(float2*)(C + (size_t)(row0+8)*N + col0) = make_float2(acc[i][j][2], acc[i][j][3]);
        }
    }
}

// ---------------- fp16 tensor-core flash self-attention -------------------------
#define KSH 24
#define VSH 1032
#define PSH 72
#define FLASH_SMEM ((1024*KSH + 16*VSH + 8*16*PSH)*2)

#define MMA_F16(acc, a, b0, b1) \
    asm volatile( \
        "mma.sync.aligned.m16n8k16.row.col.f32.f16.f16.f32 " \
        "{%0,%1,%2,%3}, {%4,%5,%6,%7}, {%8,%9}, {%0,%1,%2,%3};" \
        : "+f"((acc)[0]), "+f"((acc)[1]), "+f"((acc)[2]), "+f"((acc)[3]) \
        : "r"((a)[0]), "r"((a)[1]), "r"((a)[2]), "r"((a)[3]), \
          "r"(b0), "r"(b1))

__global__ __launch_bounds__(256) void flash_attn_kernel(
    const __half* __restrict__ qkv, __half* __restrict__ ao)
{
    extern __shared__ __half fsm[];
    __half* Ks = fsm;
    __half* Vs = fsm + 1024*KSH;
    __half* Ps = Vs + 16*VSH + (threadIdx.x >> 5)*16*PSH;

    const int b = blockIdx.x >> 6;
    const int h = blockIdx.x & 63;
    const int qt = blockIdx.y;
    const int tid = threadIdx.x;
    const int lane = tid & 31;
    const int warp = tid >> 5;
    const int qr = lane >> 2;
    const int qc = lane & 3;

    const __half* base = qkv + (size_t)b*T_SEQ*3*D + h*HD;

    for (int r = tid; r < T_SEQ; r += 256) {
        const uint32_t* kr = (const uint32_t*)(base + (size_t)r*3*D + D);
        #pragma unroll
        for (int i=0;i<8;i++) *(uint32_t*)(Ks + r*KSH + i*2) = kr[i];
        const __half* vr = base + (size_t)r*3*D + 2*D;
        #pragma unroll
        for (int d=0; d<16; d++) Vs[d*VSH + r] = vr[d];
    }

    const int q0 = qt*256 + warp*32;
    const half2 qs = __floats2half2_rn(0.25f, 0.25f);
    uint32_t aQ[2][4];
    #pragma unroll
    for (int mt=0; mt<2; mt++) {
        int r0 = q0 + mt*16 + qr;
        half2 v0 = __hmul2(*(const half2*)(base + (size_t)r0*3*D + 2*qc), qs);
        half2 v1 = __hmul2(*(const half2*)(base + (size_t)(r0+8)*3*D + 2*qc), qs);
        half2 v2 = __hmul2(*(const half2*)(base + (size_t)r0*3*D + 2*qc + 8), qs);
        half2 v3 = __hmul2(*(const half2*)(base + (size_t)(r0+8)*3*D + 2*qc + 8), qs);
        aQ[mt][0] = *(uint32_t*)&v0; aQ[mt][1] = *(uint32_t*)&v1;
        aQ[mt][2] = *(uint32_t*)&v2; aQ[mt][3] = *(uint32_t*)&v3;
    }
    __syncthreads();

    float mstate[2][2], lstate[2][2], oacc[2][2][4];
    #pragma unroll
    for (int mt=0; mt<2; mt++) {
        mstate[mt][0] = -1e30f; mstate[mt][1] = -1e30f;
        lstate[mt][0] = 0.f;    lstate[mt][1] = 0.f;
        #pragma unroll
        for (int nt=0; nt<2; nt++)
            #pragma unroll
            for (int e=0; e<4; e++) oacc[mt][nt][e] = 0.f;
    }

    for (int nc = 0; nc < 16; nc++) {
        const int kb = nc*64;
        #pragma unroll
        for (int mt=0; mt<2; mt++) {
            float sacc[8][4];
            #pragma unroll
            for (int nt=0; nt<8; nt++) {
                sacc[nt][0]=0.f; sacc[nt][1]=0.f; sacc[nt][2]=0.f; sacc[nt][3]=0.f;
                const int key = kb + nt*8 + qr;
                uint32_t b0 = *(const uint32_t*)(Ks + key*KSH + 2*qc);
                uint32_t b1 = *(const uint32_t*)(Ks + key*KSH + 2*qc + 8);
                MMA_F16(sacc[nt], aQ[mt], b0, b1);
            }
            float r0max = -1e30f, r1max = -1e30f;
            #pragma unroll
            for (int nt=0; nt<8; nt++) {
                r0max = fmaxf(r0max, fmaxf(sacc[nt][0], sacc[nt][1]));
                r1max = fmaxf(r1max, fmaxf(sacc[nt][2], sacc[nt][3]));
            }
            r0max = fmaxf(r0max, __shfl_xor_sync(0xFFFFFFFFu, r0max, 1));
            r0max = fmaxf(r0max, __shfl_xor_sync(0xFFFFFFFFu, r0max, 2));
            r1max = fmaxf(r1max, __shfl_xor_sync(0xFFFFFFFFu, r1max, 1));
            r1max = fmaxf(r1max, __shfl_xor_sync(0xFFFFFFFFu, r1max, 2));
            float mnew0 = fmaxf(mstate[mt][0], r0max);
            float mnew1 = fmaxf(mstate[mt][1], r1max);
            float corr0 = __expf(mstate[mt][0] - mnew0);
            float corr1 = __expf(mstate[mt][1] - mnew1);
            mstate[mt][0] = mnew0; mstate[mt][1] = mnew1;

            float rs0 = 0.f, rs1 = 0.f;
            #pragma unroll
            for (int nt=0; nt<8; nt++) {
                float p0 = __expf(sacc[nt][0] - mnew0);
                float p1 = __expf(sacc[nt][1] - mnew0);
                float p2 = __expf(sacc[nt][2] - mnew1);
                float p3 = __expf(sacc[nt][3] - mnew1);
                rs0 += p0 + p1; rs1 += p2 + p3;
                *(half2*)(Ps + qr*PSH + nt*8 + 2*qc)     = __floats2half2_rn(p0, p1);
                *(half2*)(Ps + (qr+8)*PSH + nt*8 + 2*qc) = __floats2half2_rn(p2, p3);
            }
            rs0 += __shfl_xor_sync(0xFFFFFFFFu, rs0, 1);
            rs0 += __shfl_xor_sync(0xFFFFFFFFu, rs0, 2);
            rs1 += __shfl_xor_sync(0xFFFFFFFFu, rs1, 1);
            rs1 += __shfl_xor_sync(0xFFFFFFFFu, rs1, 2);
            lstate[mt][0] = lstate[mt][0]*corr0 + rs0;
            lstate[mt][1] = lstate[mt][1]*corr1 + rs1;
            #pragma unroll
            for (int nt=0; nt<2; nt++) {
                oacc[mt][nt][0] *= corr0; oacc[mt][nt][1] *= corr0;
                oacc[mt][nt][2] *= corr1; oacc[mt][nt][3] *= corr1;
            }
            __syncwarp();
            #pragma unroll
            for (int ks=0; ks<4; ks++) {
                uint32_t a[4];
                a[0] = *(const uint32_t*)(Ps + qr*PSH + ks*16 + 2*qc);
                a[1] = *(const uint32_t*)(Ps + (qr+8)*PSH + ks*16 + 2*qc);
                a[2] = *(const uint32_t*)(Ps + qr*PSH + ks*16 + 2*qc + 8);
                a[3] = *(const uint32_t*)(Ps + (qr+8)*PSH + ks*16 + 2*qc + 8);
                #pragma unroll
                for (int nt=0; nt<2; nt++) {
                    const __half* vb = Vs + (nt*8+qr)*VSH + kb + ks*16;
                    uint32_t b0 = *(const uint32_t*)(vb + 2*qc);
                    uint32_t b1 = *(const uint32_t*)(vb + 2*qc + 8);
                    MMA_F16(oacc[mt][nt], a, b0, b1);
                }
            }
            __syncwarp();
        }
    }

    #pragma unroll
    for (int mt=0; mt<2; mt++) {
        float inv0 = 1.f/lstate[mt][0];
        float inv1 = 1.f/lstate[mt][1];
        int row0 = q0 + mt*16 + qr;
        #pragma unroll
        for (int nt=0; nt<2; nt++) {
            int col = h*HD + nt*8 + 2*qc;
            __half* o0 = ao + ((size_t)b*T_SEQ + row0)*D + col;
            __half* o1 = ao + ((size_t)b*T_SEQ + row0 + 8)*D + col;
            *(half2*)o0 = __floats2half2_rn(oacc[mt][nt][0]*inv0, oacc[mt][nt][1]*inv0);
            *(half2*)o1 = __floats2half2_rn(oacc[mt][nt][2]*inv1, oacc[mt][nt][3]*inv1);
        }
    }
}

// ---------------- cross-attention (folded): xo += softmax(h@K'^T/32) @ V' -------
__global__ __launch_bounds__(256) void cross_attn_kernel(
    const float* __restrict__ Q, const float* __restrict__ Km,
    const float* __restrict__ Vm, float* __restrict__ xo)
{
    extern __shared__ float csm[];
    float* Ks = csm;
    float* Vs = csm + NMEM*D;
    int b = blockIdx.x >> 2;
    int chunk = blockIdx.x & 3;
    for (int i=threadIdx.x; i<NMEM*D; i+=256) {
        Ks[i] = Km[(size_t)b*NMEM*D + i];
        Vs[i] = Vm[(size_t)b*NMEM*D + i];
    }
    __syncthreads();
    int t = chunk*256 + threadIdx.x;
    const float4* qrow = (const float4*)(Q + ((size_t)b*T_SEQ + t)*D);
    float s[16];
    #pragma unroll
    for (int mm=0;mm<16;mm++) s[mm]=0.f;
    for (int k4=0;k4<D/4;k4++) {
        float4 qv = qrow[k4];
        #pragma unroll
        for (int mm=0;mm<16;mm++) {
            const float* kr = Ks + mm*D + k4*4;
            s[mm] += qv.x*kr[0] + qv.y*kr[1] + qv.z*kr[2] + qv.w*kr[3];
        }
    }
    float mx = -1e30f;
    #pragma unroll
    for (int mm=0;mm<16;mm++) { s[mm] *= 0.03125f; mx = fmaxf(mx, s[mm]); }
    float sum = 0.f;
    #pragma unroll
    for (int mm=0;mm<16;mm++) { s[mm] = __expf(s[mm]-mx); sum += s[mm]; }
    float inv = 1.f/sum;
    #pragma unroll
    for (int mm=0;mm<16;mm++) s[mm] *= inv;
    float* xrow = xo + ((size_t)b*T_SEQ + t)*D;
    for (int c=0;c<D;c+=4) {
        float4 o = *(const float4*)(xrow + c);
        #pragma unroll
        for (int mm=0;mm<16;mm++) {
            const float* vr = Vs + mm*D + c;
            o.x += s[mm]*vr[0]; o.y += s[mm]*vr[1];
            o.z += s[mm]*vr[2]; o.w += s[mm]*vr[3];
        }
        *(float4*)(xrow + c) = o;
    }
}

// ---------------- memory path -------------------------------------------------
__global__ __launch_bounds__(256) void mean_kernel(const float* __restrict__ x,
                                                   float* __restrict__ mh) {
    __shared__ float sred[256];
    int b = blockIdx.x, cb = blockIdx.y*128;
    int c = threadIdx.x & 127, half = threadIdx.x >> 7;
    const float* p = x + (size_t)b*T_SEQ*D + (size_t)half*512*D + cb + c;
    float s = 0.f;
    #pragma unroll 4
    for (int t=0;t<512;t++) s += p[(size_t)t*D];
    sred[threadIdx.x] = s;
    __syncthreads();
    if (half == 0)
        mh[b*D + cb + c] = (sred[threadIdx.x] + sred[threadIdx.x+128]) * (1.f/T_SEQ);
}

__global__ __launch_bounds__(256) void base_gemv(
    const float* __restrict__ Wz, const float* __restrict__ Wr, const float* __restrict__ Wc,
    const float* __restrict__ bz, const float* __restrict__ br, const float* __restrict__ bc)
{
    int gid = blockIdx.x*8 + (threadIdx.x >> 5);
    int lane = threadIdx.x & 31;
    int g = gid >> 12;
    int rem = gid & 4095;
    int b = rem >> 10;
    int col = rem & 1023;
    const float* W    = (g==0) ? Wz : ((g==1) ? Wr : Wc);
    const float* bias = (g==0) ? bz : ((g==1) ? br : bc);
    const float* wrow = W + (size_t)col*2048;
    const float* mrow = g_meanh + b*D;
    float acc = 0.f;
    #pragma unroll
    for (int k0=0;k0<1024;k0+=128) {
        float4 w = *(const float4*)(wrow + k0 + lane*4);
        float4 m = *(const float4*)(mrow + k0 + lane*4);
        acc += w.x*m.x + w.y*m.y + w.z*m.z + w.w*m.w;
    }
    #pragma unroll
    for (int o=16;o;o>>=1) acc += __shfl_xor_sync(0xFFFFFFFFu, acc, o);
    if (lane == 0) g_base[gid] = acc + bias[col];
}

__device__ __forceinline__ void tile64x64(
    const float* __restrict__ A, const float* __restrict__ B, int ldb,
    float (&acc)[4][4])
{
    __shared__ float As[32][65];
    __shared__ float Bs[32][65];
    const int tid = threadIdx.x;
    const int r  = tid >> 2;
    const int kq = (tid & 3) << 3;
    const int tx = tid & 15;
    const int ty = tid >> 4;
    for (int k0 = 0; k0 < 1024; k0 += 32) {
        float4 a0 = *(const float4*)(A + (size_t)r*1024 + k0 + kq);
        float4 a1 = *(const float4*)(A + (size_t)r*1024 + k0 + kq + 4);
        float4 b0 = *(const float4*)(B + (size_t)r*ldb  + k0 + kq);
        float4 b1 = *(const float4*)(B + (size_t)r*ldb  + k0 + kq + 4);
        __syncthreads();
        As[kq+0][r]=a0.x; As[kq+1][r]=a0.y; As[kq+2][r]=a0.z; As[kq+3][r]=a0.w;
        As[kq+4][r]=a1.x; As[kq+5][r]=a1.y; As[kq+6][r]=a1.z; As[kq+7][r]=a1.w;
        Bs[kq+0][r]=b0.x; Bs[kq+1][r]=b0.y; Bs[kq+2][r]=b0.z; Bs[kq+3][r]=b0.w;
        Bs[kq+4][r]=b1.x; Bs[kq+5][r]=b1.y; Bs[kq+6][r]=b1.z; Bs[kq+7][r]=b1.w;
        __syncthreads();
        #pragma unroll
        for (int kk=0;kk<32;kk++) {
            float a[4], b[4];
            #pragma unroll
            for (int i=0;i<4;i++) a[i] = As[kk][ty*4+i];
            #pragma unroll
            for (int j=0;j<4;j++) b[j] = Bs[kk][tx*4+j];
            #pragma unroll
            for (int i=0;i<4;i++)
                #pragma unroll
                for (int j=0;j<4;j++) acc[i][j] += a[i]*b[j];
        }
    }
}

__global__ __launch_bounds__(256) void zr_pre(
    const float* __restrict__ mem, const float* __restrict__ Wz,
    const float* __restrict__ Wr)
{
    int g = blockIdx.y;
    int ct = blockIdx.x;
    const float* W = (g ? Wr : Wz) + (size_t)(ct*64)*2048 + 1024;
    float acc[4][4];
    #pragma unroll
    for (int i=0;i<4;i++)
        #pragma unroll
        for (int j=0;j<4;j++) acc[i][j]=0.f;
    tile64x64(mem, W, 2048, acc);
    float* out = g ? g_rpre : g_zpre;
    const int tx = threadIdx.x & 15, ty = threadIdx.x >> 4;
    #pragma unroll
    for (int i=0;i<4;i++) {
        int row = ty*4+i;
        #pragma unroll
        for (int j=0;j<4;j++) out[row*1024 + ct*64 + tx*4+j] = acc[i][j];
    }
}

__global__ void combine_kernel(const float* __restrict__ mem) {
    int idx = blockIdx.x*blockDim.x + threadIdx.x;
    int row = idx >> 10, col = idx & 1023, b = row >> 4;
    float z = 1.f/(1.f + __expf(-(g_zpre[idx] + g_base[0*4096 + b*1024 + col])));
    float r = 1.f/(1.f + __expf(-(g_rpre[idx] + g_base[1*4096 + b*1024 + col])));
    g_z[idx] = z;
    g_rm[idx] = r * mem[idx];
}

__global__ __launch_bounds__(256) void c_gemm(
    const float* __restrict__ mem, const float* __restrict__ Wc,
    float* __restrict__ newmem)
{
    int ct = blockIdx.x;
    const float* W = Wc + (size_t)(ct*64)*2048 + 1024;
    float acc[4][4];
    #pragma unroll
    for (int i=0;i<4;i++)
        #pragma unroll
        for (int j=0;j<4;j++) acc[i][j]=0.f;
    tile64x64(g_rm, W, 2048, acc);
    const int tx = threadIdx.x & 15, ty = threadIdx.x >> 4;
    #pragma unroll
    for (int i=0;i<4;i++) {
        int row = ty*4+i;
        #pragma unroll
        for (int j=0;j<4;j++) {
            int col = ct*64 + tx*4+j;
            float v = acc[i][j] + g_base[2*4096 + (row>>4)*1024 + col];
            float c = tanhf(v);
            float z = g_z[row*1024+col];
            newmem[(size_t)row*1024+col] = (1.f - z)*mem[(size_t)row*1024+col] + z*c;
        }
    }
}

__global__ __launch_bounds__(256) void kv2_gemm(const float* __restrict__ newmem)
{
    int which = blockIdx.y;
    int ct = blockIdx.x;
    const float* W = (which ? g_wv : g_wk) + (size_t)(ct*64)*1024;
    float acc[4][4];
    #pragma unroll
    for (int i=0;i<4;i++)
        #pragma unroll
        for (int j=0;j<4;j++) acc[i][j]=0.f;
    tile64x64(newmem, W, 1024, acc);
    float* out = which ? g_V : g_K;
    const int tx = threadIdx.x & 15, ty = threadIdx.x >> 4;
    #pragma unroll
    for (int i=0;i<4;i++) {
        int row = ty*4+i;
        #pragma unroll
        for (int j=0;j<4;j++) {
            int col = ct*64 + tx*4+j;
            out[(size_t)row*1024+col] = acc[i][j];
        }
    }
}

// ---------------- host launcher -------------------------------------------------
extern "C" void kernel_launch(void* const* d_in, const int* in_sizes, int n_in,
                              void* d_out, int out_size)
{
    const float* x          = (const float*)d_in[0];
    const float* memory     = (const float*)d_in[1];
    const float* ln1_g      = (const float*)d_in[2];
    const float* ln1_b      = (const float*)d_in[3];
    const float* ln2_g      = (const float*)d_in[4];
    const float* ln2_b      = (const float*)d_in[5];
    const float* ln3_g      = (const float*)d_in[6];
    const float* ln3_b      = (const float*)d_in[7];
    const float* in_proj_w  = (const float*)d_in[8];
    const float* in_proj_b  = (const float*)d_in[9];
    const float* attn_out_w = (const float*)d_in[10];
    const float* attn_out_b = (const float*)d_in[11];
    const float* Wz_w       = (const float*)d_in[12];
    const float* Wz_b       = (const float*)d_in[13];
    const float* Wr_w       = (const float*)d_in[14];
    const float* Wr_b       = (const float*)d_in[15];
    const float* Wc_w       = (const float*)d_in[16];
    const float* Wc_b       = (const float*)d_in[17];
    const float* mq_w       = (const float*)d_in[18];
    const float* mk_w       = (const float*)d_in[19];
    const float* mv_w       = (const float*)d_in[20];
    const float* mo_w       = (const float*)d_in[21];
    const float* W1         = (const float*)d_in[22];
    const float* b1         = (const float*)d_in[23];
    const float* W2         = (const float*)d_in[24];
    const float* b2         = (const float*)d_in[25];

    float* xo = (float*)d_out;
    float* newmem = xo + (size_t)ROWS*D;

    float *p_h, *p_K, *p_V, *p_w, *p_mh, *p_wk, *p_wv;
    __half *p_hh, *p_hqkv, *p_hao, *p_hffn, *p_hw;
    cudaGetSymbolAddress((void**)&p_h,    g_h);
    cudaGetSymbolAddress((void**)&p_K,    g_K);
    cudaGetSymbolAddress((void**)&p_V,    g_V);
    cudaGetSymbolAddress((void**)&p_w,    g_w);
    cudaGetSymbolAddress((void**)&p_mh,   g_meanh);
    cudaGetSymbolAddress((void**)&p_wk,   g_wk);
    cudaGetSymbolAddress((void**)&p_wv,   g_wv);
    cudaGetSymbolAddress((void**)&p_hh,   h_h);
    cudaGetSymbolAddress((void**)&p_hqkv, h_qkv);
    cudaGetSymbolAddress((void**)&p_hao,  h_ao);
    cudaGetSymbolAddress((void**)&p_hffn, h_ffn);
    cudaGetSymbolAddress((void**)&p_hw,   h_w);

    static cudaStream_t s2 = nullptr;
    static cudaEvent_t evStart = nullptr, evCvt = nullptr, evFork = nullptr, evMem = nullptr;
    static bool tried = false, ok = false;
    if (!tried) {
        tried = true;
        ok = (cudaStreamCreateWithFlags(&s2, cudaStreamNonBlocking) == cudaSuccess) &&
             (cudaEventCreateWithFlags(&evStart, cudaEventDisableTiming) == cudaSuccess) &&
             (cudaEventCreateWithFlags(&evCvt,   cudaEventDisableTiming) == cudaSuccess) &&
             (cudaEventCreateWithFlags(&evFork,  cudaEventDisableTiming) == cudaSuccess) &&
             (cudaEventCreateWithFlags(&evMem,   cudaEventDisableTiming) == cudaSuccess);
    }
    cudaStream_t sb = ok ? s2 : (cudaStream_t)0;

    cudaFuncSetAttribute(flash_attn_kernel, cudaFuncAttributeMaxDynamicSharedMemorySize, FLASH_SMEM);
    cudaFuncSetAttribute(cross_attn_kernel, cudaFuncAttributeMaxDynamicSharedMemorySize, 131072);
    const int GSM = SMEM_FLOATS * 4;
    cudaFuncSetAttribute(gemm_tf32<0,0,0,0>, cudaFuncAttributeMaxDynamicSharedMemorySize, GSM);
    cudaFuncSetAttribute(gemm_fp16<0,1,0,1>, cudaFuncAttributeMaxDynamicSharedMemorySize, HSMEM_BYTES);
    cudaFuncSetAttribute(gemm_fp16<0,1,1,0>, cudaFuncAttributeMaxDynamicSharedMemorySize, HSMEM_BYTES);
    cudaFuncSetAttribute(gemm_fp16<1,1,0,1>, cudaFuncAttributeMaxDynamicSharedMemorySize, HSMEM_BYTES);

    // ---- early hidden phase on sb ----
    if (ok) { cudaEventRecord(evStart, 0); cudaStreamWaitEvent(sb, evStart, 0); }
    cvt_fp16_kernel<<<3072, 256, 0, sb>>>(in_proj_w,  p_hw + HOFF_INP,  3*1024*1024/4);
    cvt_fp16_kernel<<<1024, 256, 0, sb>>>(attn_out_w, p_hw + HOFF_AOUT, 1024*1024/4);
    cvt_fp16_kernel<<<4096, 256, 0, sb>>>(W1,         p_hw + HOFF_W1,   4*1024*1024/4);
    cvt_fp16_kernel<<<4096, 256, 0, sb>>>(W2,         p_hw + HOFF_W2,   4*1024*1024/4);
    if (ok) cudaEventRecord(evCvt, sb);
    cvt_tf32_kernel<<<1024, 256, 0, sb>>>(mo_w, p_w + OFF_MO, 1024*1024/4);
    transpose_tf32<<<dim3(32,32), dim3(32,8), 0, sb>>>(mq_w, p_w + OFF_MQT);
    transpose_tf32<<<dim3(32,32), dim3(32,8), 0, sb>>>(mk_w, p_w + OFF_MKT);
    transpose_tf32<<<dim3(32,32), dim3(32,8), 0, sb>>>(mv_w, p_w + OFF_MVT);
    gemm_tf32<0,0,0,0><<<dim3(8,8), 256, GSM, sb>>>(p_w + OFF_MQT, p_w + OFF_MKT, nullptr, nullptr, p_wk, 1024, 1024, 1024);
    gemm_tf32<0,0,0,0><<<dim3(8,8), 256, GSM, sb>>>(p_w + OFF_MO,  p_w + OFF_MVT, nullptr, nullptr, p_wv, 1024, 1024, 1024);
    zr_pre<<<dim3(16,2), 256, 0, sb>>>(memory, Wz_w, Wr_w);

    // ---- main path ----
    ln_kernel_h<<<ROWS, 256>>>(x, ln1_g, ln1_b, p_hh);
    if (ok) cudaStreamWaitEvent(0, evCvt, 0);

    gemm_fp16<0,1,0,1><<<dim3(3*D/128, ROWS/128), 256, HSMEM_BYTES>>>(p_hh, p_hw + HOFF_INP, in_proj_b, nullptr, p_hqkv, ROWS, 3*D, D);
    flash_attn_kernel<<<dim3(BATCH*NHEADS, 4), 256, FLASH_SMEM>>>(p_hqkv, p_hao);
    gemm_fp16<0,1,1,0><<<dim3(D/128, ROWS/128), 256, HSMEM_BYTES>>>(p_hao, p_hw + HOFF_AOUT, attn_out_b, x, xo, ROWS, D, D);

    // ---- fork memory path onto sb ----
    if (ok) { cudaEventRecord(evFork, 0); cudaStreamWaitEvent(sb, evFork, 0); }
    mean_kernel<<<dim3(BATCH, 8), 256, 0, sb>>>(xo, p_mh);
    base_gemv<<<1536, 256, 0, sb>>>(Wz_w, Wr_w, Wc_w, Wz_b, Wr_b, Wc_b);
    combine_kernel<<<BATCH*NMEM*D/256, 256, 0, sb>>>(memory);
    c_gemm<<<16, 256, 0, sb>>>(memory, Wc_w, newmem);
    kv2_gemm<<<dim3(16, 2), 256, 0, sb>>>(newmem);
    if (ok) cudaEventRecord(evMem, sb);

    // ---- main path: LN2 (overlaps memory-path tail), then cross-attention ----
    ln_kernel<<<ROWS, 256>>>(xo, ln2_g, ln2_b, p_h);
    if (ok) cudaStreamWaitEvent(0, evMem, 0);
    cross_attn_kernel<<<BATCH*4, 256, 131072>>>(p_h, p_K, p_V, xo);

    // FFN
    ln_kernel_h<<<ROWS, 256>>>(xo, ln3_g, ln3_b, p_hh);
    gemm_fp16<1,1,0,1><<<dim3(4*D/128, ROWS/128), 256, HSMEM_BYTES>>>(p_hh, p_hw + HOFF_W1, b1, nullptr, p_hffn, ROWS, 4*D, D);
    gemm_fp16<0,1,1,0><<<dim3(D/128, ROWS/128), 256, HSMEM_BYTES>>>(p_hffn, p_hw + HOFF_W2, b2, xo, xo, ROWS, D, 4*D);
}